// round 8
// baseline (speedup 1.0000x reference)
#include <cuda_runtime.h>
#include <math.h>

#define B_      4
#define S_      4096
#define S2_     2048
#define D_      1024
#define SCAFD_  768
#define H_      8
#define HD_     128
#define KSEL_   2549                 // int(4096 * sigmoid(0.5))
#define BKROWS_ (B_*KSEL_)           // 10196

// ---------------- scratch ----------------------------------------------------
// Heavy scratch minimized: k, v, attn share ONE workspace (attn overlays dead
// k and the head of dead v). q/o and scaf live inside d_out (the harness's
// output buffer) until the final fuse pass rewrites it.
//   d_ws layout (floats):
//     [0,        8388608)  k   (live: qkv GEMM .. flash)
//     [8388608, 16777216)  v   (live: qkv GEMM .. flash)
//     [0,       10440704)  attn_out (live: attn GEMM .. final; k/v dead then)
#define WS_K    0L
#define WS_V    8388608L
#define WS_ATTN 0L
__device__ float d_ws[16777216];     // 67.1 MB
__device__ float d_scores[B_*S_];
__device__ float d_gatel [B_*S_];
__device__ int   d_grows [BKROWS_];
__device__ int   d_rowof [B_*S_];
__device__ int   d_cnt   [B_];
__device__ float d_confsum;

// ---------------- init -------------------------------------------------------
__global__ void init_kernel() {
    int i = blockIdx.x * blockDim.x + threadIdx.x;
    if (i < B_*S_) d_rowof[i] = -1;
    if (i < B_)    d_cnt[i]   = 0;
    if (i == 0)    d_confsum  = 0.0f;
}

// ---------------- per-row dual dot (topk score + gate logit), fp32 exact -----
__global__ void rowdot2_kernel(const float* __restrict__ X,
                               const float* __restrict__ w1,
                               const float* __restrict__ b1,
                               const float* __restrict__ w2,
                               const float* __restrict__ b2,
                               float* __restrict__ out1,
                               float* __restrict__ out2,
                               int nrows, int dim) {
    int warp = (blockIdx.x * blockDim.x + threadIdx.x) >> 5;
    int lane = threadIdx.x & 31;
    if (warp >= nrows) return;
    const float4* x4  = (const float4*)(X + (long)warp * dim);
    const float4* w14 = (const float4*)w1;
    const float4* w24 = (const float4*)w2;
    float s1 = 0.0f, s2 = 0.0f;
    for (int i = lane; i < dim / 4; i += 32) {
        float4 a = x4[i];
        float4 u = w14[i];
        float4 v = w24[i];
        s1 += a.x*u.x + a.y*u.y + a.z*u.z + a.w*u.w;
        s2 += a.x*v.x + a.y*v.y + a.z*v.z + a.w*v.w;
    }
    #pragma unroll
    for (int off = 16; off; off >>= 1) {
        s1 += __shfl_xor_sync(0xffffffffu, s1, off);
        s2 += __shfl_xor_sync(0xffffffffu, s2, off);
    }
    if (lane == 0) {
        out1[warp] = s1 + b1[0];
        out2[warp] = s2 + b2[0];
    }
}

// ---------------- mean row-norm of scaf (confidence) -------------------------
__global__ void norm_kernel(const float* __restrict__ scaf) {
    int warp = (blockIdx.x * blockDim.x + threadIdx.x) >> 5;
    int lane = threadIdx.x & 31;
    if (warp >= B_*S2_) return;
    const float4* x4 = (const float4*)(scaf + (long)warp * D_);
    float s = 0.0f;
    for (int i = lane; i < D_/4; i += 32) {
        float4 a = x4[i];
        s += a.x*a.x + a.y*a.y + a.z*a.z + a.w*a.w;
    }
    #pragma unroll
    for (int off = 16; off; off >>= 1) s += __shfl_xor_sync(0xffffffffu, s, off);
    if (lane == 0) atomicAdd(&d_confsum, sqrtf(s));
}

// ---------------- exact top-K set selection via rank counting ----------------
// rank(s) = #{s': score>} + #{s'<s: score==} -> selected iff rank < K.
// Matches jax.lax.top_k tie-breaking (lower index first). Exactly K selected.
__global__ void select_kernel() {
    __shared__ float sh[S_];
    int b = blockIdx.x;
    const float* sc = d_scores + b * S_;
    for (int i = threadIdx.x; i < S_; i += blockDim.x) sh[i] = sc[i];
    __syncthreads();
    const int NPT = S_ / 1024;       // 4
    float myv[NPT]; int mys[NPT]; int cg[NPT], ce[NPT];
    #pragma unroll
    for (int i = 0; i < NPT; i++) {
        mys[i] = threadIdx.x + i * 1024;
        myv[i] = sh[mys[i]];
        cg[i] = 0; ce[i] = 0;
    }
    for (int j = 0; j < S_; ++j) {
        float v = sh[j];
        #pragma unroll
        for (int i = 0; i < NPT; i++) {
            cg[i] += (v > myv[i]);
            ce[i] += (v == myv[i] && j < mys[i]);
        }
    }
    #pragma unroll
    for (int i = 0; i < NPT; i++) {
        if (cg[i] + ce[i] < KSEL_) {
            int pos = atomicAdd(&d_cnt[b], 1);
            d_grows[b * KSEL_ + pos]  = b * S_ + mys[i];
            d_rowof[b * S_ + mys[i]]  = b * KSEL_ + pos;
        }
    }
}

// ---------------- generic fp32 SGEMM: C = A @ op(B) + bias -------------------
#define BM 128
#define BN 128
#define BKT 16

template <bool BT, bool GATHER>
__global__ __launch_bounds__(256)
void sgemm_kernel(const float* __restrict__ A, const float* __restrict__ Bm,
                  const float* __restrict__ bias, float* __restrict__ C,
                  const int* __restrict__ grows,
                  int M, int N, int Kd, int lda, int ldb, int ldc) {
    __shared__ float As[BKT][BM];
    __shared__ float Bs[BKT][BN + 4];

    const int tid = threadIdx.x;
    const int bm  = blockIdx.y * BM;
    const int bn  = blockIdx.x * BN;
    const int tx  = tid & 15, ty = tid >> 4;

    const int la_row = tid >> 2;          // 0..63
    const int la_col = (tid & 3) << 2;    // 0,4,8,12
    const int lb_row = tid >> 5;          // 0..7
    const int lb_col = (tid & 31) << 2;   // 0..124

    float acc[8][8];
    #pragma unroll
    for (int i = 0; i < 8; i++)
        #pragma unroll
        for (int j = 0; j < 8; j++) acc[i][j] = 0.0f;

    for (int k0 = 0; k0 < Kd; k0 += BKT) {
        #pragma unroll
        for (int i = 0; i < 2; i++) {
            int m = bm + la_row + i * 64;
            float4 av = make_float4(0.f, 0.f, 0.f, 0.f);
            if (m < M) {
                long src = GATHER ? (long)grows[m] : (long)m;
                av = *(const float4*)(A + src * lda + k0 + la_col);
            }
            As[la_col + 0][la_row + i * 64] = av.x;
            As[la_col + 1][la_row + i * 64] = av.y;
            As[la_col + 2][la_row + i * 64] = av.z;
            As[la_col + 3][la_row + i * 64] = av.w;
        }
        if (BT) {
            #pragma unroll
            for (int i = 0; i < 2; i++) {
                int n = bn + la_row + i * 64;      // N always multiple of 128
                float4 bv = *(const float4*)(Bm + (long)n * ldb + k0 + la_col);
                Bs[la_col + 0][la_row + i * 64] = bv.x;
                Bs[la_col + 1][la_row + i * 64] = bv.y;
                Bs[la_col + 2][la_row + i * 64] = bv.z;
                Bs[la_col + 3][la_row + i * 64] = bv.w;
            }
        } else {
            #pragma unroll
            for (int i = 0; i < 2; i++) {
                int kk = lb_row + i * 8;
                float4 bv = *(const float4*)(Bm + (long)(k0 + kk) * ldb + bn + lb_col);
                *(float4*)&Bs[kk][lb_col] = bv;
            }
        }
        __syncthreads();

        #pragma unroll
        for (int kk = 0; kk < BKT; ++kk) {
            float4 a0 = *(const float4*)&As[kk][ty * 8];
            float4 a1 = *(const float4*)&As[kk][ty * 8 + 4];
            float4 b0 = *(const float4*)&Bs[kk][tx * 8];
            float4 b1 = *(const float4*)&Bs[kk][tx * 8 + 4];
            float ra[8] = {a0.x, a0.y, a0.z, a0.w, a1.x, a1.y, a1.z, a1.w};
            float rb[8] = {b0.x, b0.y, b0.z, b0.w, b1.x, b1.y, b1.z, b1.w};
            #pragma unroll
            for (int i = 0; i < 8; i++)
                #pragma unroll
                for (int j = 0; j < 8; j++)
                    acc[i][j] += ra[i] * rb[j];
        }
        __syncthreads();
    }

    #pragma unroll
    for (int i = 0; i < 8; i++) {
        int m = bm + ty * 8 + i;
        if (m >= M) continue;
        #pragma unroll
        for (int j = 0; j < 8; j += 4) {
            int n = bn + tx * 8 + j;
            float4 r;
            r.x = acc[i][j + 0];
            r.y = acc[i][j + 1];
            r.z = acc[i][j + 2];
            r.w = acc[i][j + 3];
            if (bias) {
                r.x += bias[n + 0]; r.y += bias[n + 1];
                r.z += bias[n + 2]; r.w += bias[n + 3];
            }
            *(float4*)(C + (long)m * ldc + n) = r;
        }
    }
}

// ---------------- fused flash attention --------------------------------------
// Per block: one 64-query tile of one (b,h). Online softmax over 32 key tiles
// of 64. Q scaled by 1/sqrt(HD) at load. O written IN-PLACE over Q (each block
// reads its Q region into smem before writing the same region; regions are
// disjoint across blocks).
// Thread map (256 thr): ty=tid/16 (0..15) owns q-rows ty*4+{0..3};
//   S phase: tx owns k-cols tx*4+{0..3};  PV phase: tx owns d-cols tx*8+{0..7}.
// smem: Qt[128][64] (transposed, scaled), Kt[128][64] (transposed),
//       Vs[64][128] (natural), Ps[64][68]. Total 115712 B (dynamic).
__global__ __launch_bounds__(256)
void flash_kernel(float* __restrict__ qo,
                  const float* __restrict__ kbuf,
                  const float* __restrict__ vbuf) {
    const int qt = blockIdx.x, h = blockIdx.y, b = blockIdx.z;
    const int tid = threadIdx.x;
    const int tx = tid & 15, ty = tid >> 4;
    const float scale = 0.08838834764831845f;   // 1/sqrt(128)

    extern __shared__ float sm[];
    float* Qt = sm;            // 128*64
    float* Kt = sm + 8192;     // 128*64
    float* Vs = sm + 16384;    // 64*128
    float* Ps = sm + 24576;    // 64*68

    const int qrow0 = qt * 64;
    float* qbase = qo + (long)b * KSEL_ * D_ + (long)h * HD_;
    const float* kbase = kbuf + (long)b * S2_ * D_ + (long)h * HD_;
    const float* vbase = vbuf + (long)b * S2_ * D_ + (long)h * HD_;

    // load Q tile transposed + scaled (zero-pad rows >= KSEL_)
    for (int v = tid; v < 64 * 32; v += 256) {
        int row = v >> 5, kv = v & 31;
        float4 val = make_float4(0.f, 0.f, 0.f, 0.f);
        int gr = qrow0 + row;
        if (gr < KSEL_) val = *(const float4*)(qbase + (long)gr * D_ + kv * 4);
        int k0 = kv * 4;
        Qt[(k0 + 0) * 64 + row] = val.x * scale;
        Qt[(k0 + 1) * 64 + row] = val.y * scale;
        Qt[(k0 + 2) * 64 + row] = val.z * scale;
        Qt[(k0 + 3) * 64 + row] = val.w * scale;
    }

    float o[4][8];
    #pragma unroll
    for (int i = 0; i < 4; i++)
        #pragma unroll
        for (int j = 0; j < 8; j++) o[i][j] = 0.0f;
    float m_run[4] = {-1e30f, -1e30f, -1e30f, -1e30f};
    float l_run[4] = {0.f, 0.f, 0.f, 0.f};

    for (int t = 0; t < S2_ / 64; ++t) {
        __syncthreads();   // also protects Qt on first iter / Ps,Vs reuse after
        // load K (transposed) + V (natural) tiles
        for (int v = tid; v < 64 * 32; v += 256) {
            int row = v >> 5, kv = v & 31;
            long goff = (long)(t * 64 + row) * D_ + kv * 4;
            float4 kval = *(const float4*)(kbase + goff);
            int k0 = kv * 4;
            Kt[(k0 + 0) * 64 + row] = kval.x;
            Kt[(k0 + 1) * 64 + row] = kval.y;
            Kt[(k0 + 2) * 64 + row] = kval.z;
            Kt[(k0 + 3) * 64 + row] = kval.w;
            *(float4*)(Vs + row * 128 + kv * 4) = *(const float4*)(vbase + goff);
        }
        __syncthreads();

        // S tile: s[4][4] = Q(4 rows) . K(4 cols)
        float s[4][4];
        #pragma unroll
        for (int i = 0; i < 4; i++)
            #pragma unroll
            for (int j = 0; j < 4; j++) s[i][j] = 0.0f;
        for (int k = 0; k < 128; ++k) {
            float4 qv = *(const float4*)(Qt + k * 64 + ty * 4);
            float4 kv4 = *(const float4*)(Kt + k * 64 + tx * 4);
            float qa[4] = {qv.x, qv.y, qv.z, qv.w};
            float ka[4] = {kv4.x, kv4.y, kv4.z, kv4.w};
            #pragma unroll
            for (int i = 0; i < 4; i++)
                #pragma unroll
                for (int j = 0; j < 4; j++)
                    s[i][j] += qa[i] * ka[j];
        }

        // online softmax update (reductions across the 16-lane tx group)
        #pragma unroll
        for (int i = 0; i < 4; i++) {
            float rm = fmaxf(fmaxf(s[i][0], s[i][1]), fmaxf(s[i][2], s[i][3]));
            #pragma unroll
            for (int off = 1; off < 16; off <<= 1)
                rm = fmaxf(rm, __shfl_xor_sync(0xffffffffu, rm, off));
            float mnew = fmaxf(m_run[i], rm);
            float corr = __expf(m_run[i] - mnew);
            float psum = 0.0f;
            #pragma unroll
            for (int j = 0; j < 4; j++) {
                float p = __expf(s[i][j] - mnew);
                s[i][j] = p;
                psum += p;
            }
            #pragma unroll
            for (int off = 1; off < 16; off <<= 1)
                psum += __shfl_xor_sync(0xffffffffu, psum, off);
            l_run[i] = l_run[i] * corr + psum;
            m_run[i] = mnew;
            #pragma unroll
            for (int j = 0; j < 8; j++) o[i][j] *= corr;
        }

        // stage P tile
        #pragma unroll
        for (int i = 0; i < 4; i++)
            *(float4*)(Ps + (ty * 4 + i) * 68 + tx * 4) =
                make_float4(s[i][0], s[i][1], s[i][2], s[i][3]);
        __syncthreads();

        // O += P @ V
        for (int kk = 0; kk < 64; ++kk) {
            float p0 = Ps[(ty * 4 + 0) * 68 + kk];
            float p1 = Ps[(ty * 4 + 1) * 68 + kk];
            float p2 = Ps[(ty * 4 + 2) * 68 + kk];
            float p3 = Ps[(ty * 4 + 3) * 68 + kk];
            float4 v0 = *(const float4*)(Vs + kk * 128 + tx * 8);
            float4 v1 = *(const float4*)(Vs + kk * 128 + tx * 8 + 4);
            float va[8] = {v0.x, v0.y, v0.z, v0.w, v1.x, v1.y, v1.z, v1.w};
            float pa[4] = {p0, p1, p2, p3};
            #pragma unroll
            for (int i = 0; i < 4; i++)
                #pragma unroll
                for (int j = 0; j < 8; j++)
                    o[i][j] += pa[i] * va[j];
        }
    }

    // epilogue: normalize + write in-place over Q
    #pragma unroll
    for (int i = 0; i < 4; i++) {
        int gr = qrow0 + ty * 4 + i;
        if (gr >= KSEL_) continue;
        float inv = 1.0f / l_run[i];
        float4 r0, r1;
        r0.x = o[i][0] * inv; r0.y = o[i][1] * inv;
        r0.z = o[i][2] * inv; r0.w = o[i][3] * inv;
        r1.x = o[i][4] * inv; r1.y = o[i][5] * inv;
        r1.z = o[i][6] * inv; r1.w = o[i][7] * inv;
        *(float4*)(qbase + (long)gr * D_ + tx * 8)     = r0;
        *(float4*)(qbase + (long)gr * D_ + tx * 8 + 4) = r1;
    }
}

// ---------------- final fuse -------------------------------------------------
// out = conf_ok ? base + 0.5*gate*(selected ? attn_out : base) : base
__global__ void final_kernel(const float* __restrict__ base,
                             const float* __restrict__ attn,
                             const float* __restrict__ cth,
                             float* __restrict__ out) {
    int row = blockIdx.x;                       // B*S rows
    int tid = threadIdx.x;                      // 256 threads, D/4 float4
    bool ok = (d_confsum * (1.0f / (float)(B_ * S2_)) > cth[0]);
    float g  = 1.0f / (1.0f + expf(-d_gatel[row]));
    float hg = 0.5f * g;
    int ro   = d_rowof[row];
    const float4* bp = (const float4*)(base + (long)row * D_);
    const float4* ap = (ro >= 0) ? (const float4*)(attn + (long)ro * D_) : bp;
    float4* op = (float4*)(out + (long)row * D_);
    float4 x = bp[tid];
    float4 a = ap[tid];
    float4 y;
    y.x = ok ? x.x + hg * a.x : x.x;
    y.y = ok ? x.y + hg * a.y : x.y;
    y.z = ok ? x.z + hg * a.z : x.z;
    y.w = ok ? x.w + hg * a.w : x.w;
    op[tid] = y;
}

// ---------------- host orchestration -----------------------------------------
static void run_sgemm(bool bt, bool gather,
                      const float* A, const float* Bm, const float* bias, float* C,
                      const int* grows, int M, int N, int Kd,
                      int lda, int ldb, int ldc) {
    dim3 grid(N / BN, (M + BM - 1) / BM, 1);
    if (bt) {
        if (gather)
            sgemm_kernel<true, true><<<grid, 256>>>(A, Bm, bias, C, grows,
                                                    M, N, Kd, lda, ldb, ldc);
        else
            sgemm_kernel<true, false><<<grid, 256>>>(A, Bm, bias, C, grows,
                                                     M, N, Kd, lda, ldb, ldc);
    } else {
        sgemm_kernel<false, false><<<grid, 256>>>(A, Bm, bias, C, grows,
                                                  M, N, Kd, lda, ldb, ldc);
    }
}

extern "C" void kernel_launch(void* const* d_in, const int* in_sizes, int n_in,
                              void* d_out, int out_size) {
    const float* base     = (const float*)d_in[0];   // (B,S,D)
    const float* scaffold = (const float*)d_in[1];   // (B,S2,SCAF_D)
    const float* spw      = (const float*)d_in[2];   // (D,SCAF_D)
    const float* spb      = (const float*)d_in[3];   // (D,)
    const float* tkw      = (const float*)d_in[4];   // (1,D)
    const float* tkb      = (const float*)d_in[5];   // (1,)
    const float* ipw      = (const float*)d_in[6];   // (3D,D)
    const float* ipb      = (const float*)d_in[7];   // (3D,)
    const float* opw      = (const float*)d_in[8];   // (D,D)
    const float* opb      = (const float*)d_in[9];   // (D,)
    const float* gw       = (const float*)d_in[10];  // (1,D)
    const float* gb       = (const float*)d_in[11];  // (1,)
    const float* cth      = (const float*)d_in[12];  // (1,)
    float* out            = (float*)d_out;

    float* p_ws;
    float* p_scores; float* p_gatel; int* p_grows;
    cudaGetSymbolAddress((void**)&p_ws,     d_ws);
    cudaGetSymbolAddress((void**)&p_scores, d_scores);
    cudaGetSymbolAddress((void**)&p_gatel,  d_gatel);
    cudaGetSymbolAddress((void**)&p_grows,  d_grows);

    float* p_k    = p_ws + WS_K;
    float* p_v    = p_ws + WS_V;
    float* p_attn = p_ws + WS_ATTN;
    float* p_scaf = out;               // scaf staged in d_out (dead before q)
    float* p_qo   = out;               // q, then o in-place; dead before final

    // allow >48KB dynamic smem for the flash kernel (idempotent host call)
    cudaFuncSetAttribute(flash_kernel,
                         cudaFuncAttributeMaxDynamicSharedMemorySize, 115712);

    // 1) init small state
    init_kernel<<<64, 256>>>();

    // 2) fp32-exact topk scores + gate logits in one pass over base
    rowdot2_kernel<<<(B_ * S_ * 32 + 255) / 256, 256>>>(
        base, tkw, tkb, gw, gb, p_scores, p_gatel, B_ * S_, D_);

    // 3) exact top-K set per batch
    select_kernel<<<B_, 1024>>>();

    // 4) scaf = scaffold @ spw^T + spb  (8192 x 1024 x 768) -> d_out
    run_sgemm(true, false, scaffold, spw, spb, p_scaf, nullptr,
              B_ * S2_, D_, SCAFD_, SCAFD_, SCAFD_, D_);

    // 5) confidence = mean row norm of scaf
    norm_kernel<<<(B_ * S2_ * 32 + 255) / 256, 256>>>(p_scaf);

    // 6) k = scaf @ wk^T + bk ; v = scaf @ wv^T + bv  -> d_ws
    run_sgemm(true, false, p_scaf, ipw + (long)D_ * D_, ipb + D_, p_k, nullptr,
              B_ * S2_, D_, D_, D_, D_, D_);
    run_sgemm(true, false, p_scaf, ipw + 2L * D_ * D_, ipb + 2 * D_, p_v, nullptr,
              B_ * S2_, D_, D_, D_, D_, D_);

    // 7) q = gather(base) @ wq^T + bq  (10196 x 1024 x 1024) -> d_out (scaf dead)
    run_sgemm(true, true, base, ipw, ipb, p_qo, p_grows,
              BKROWS_, D_, D_, D_, D_, D_);

    // 8+9+10) fused flash attention; o overwrites q in-place
    {
        dim3 grid((KSEL_ + 63) / 64, H_, B_);
        flash_kernel<<<grid, 256, 115712>>>(p_qo, p_k, p_v);
    }

    // 11) attn_out = o @ opw^T + opb -> d_ws (overlays dead k)
    run_sgemm(true, false, p_qo, opw, opb, p_attn, nullptr,
              BKROWS_, D_, D_, D_, D_, D_);

    // 12) fuse (rewrites all of d_out; o dead)
    final_kernel<<<B_ * S_, 256>>>(base, p_attn, cth, out);
}

// round 9
// speedup vs baseline: 2.9944x; 2.9944x over previous
#include <cuda_runtime.h>
#include <math.h>
#include <stdint.h>

#define B_      4
#define S_      4096
#define S2_     2048
#define D_      1024
#define SCAFD_  768
#define H_      8
#define HD_     128
#define KSEL_   2549                 // int(4096 * sigmoid(0.5))
#define BKROWS_ (B_*KSEL_)           // 10196

// ---------------- scratch ----------------------------------------------------
//   d_ws layout (floats):
//     [0,        8388608)  k        (live: qkv GEMM .. flash)
//     [8388608, 16777216)  v        (live: qkv GEMM .. flash)
//     [0,       10440704)  attn_out (live: attn GEMM .. final; k/v dead then)
#define WS_K    0L
#define WS_V    8388608L
#define WS_ATTN 0L
__device__ float d_ws[16777216];     // 67.1 MB
__device__ float d_scores[B_*S_];
__device__ float d_gatel [B_*S_];
__device__ int   d_grows [BKROWS_];
__device__ int   d_rowof [B_*S_];
__device__ int   d_cnt   [B_];
__device__ float d_confsum;

// ---------------- tf32 mma helper --------------------------------------------
__device__ __forceinline__ void mma_tf32(float& d0, float& d1, float& d2, float& d3,
                                         float a0, float a1, float a2, float a3,
                                         float b0, float b1) {
    uint32_t A0 = __float_as_uint(a0), A1 = __float_as_uint(a1);
    uint32_t A2 = __float_as_uint(a2), A3 = __float_as_uint(a3);
    uint32_t B0 = __float_as_uint(b0), B1 = __float_as_uint(b1);
    asm volatile(
        "mma.sync.aligned.m16n8k8.row.col.f32.tf32.tf32.f32 "
        "{%0,%1,%2,%3}, {%4,%5,%6,%7}, {%8,%9}, {%0,%1,%2,%3};"
        : "+f"(d0), "+f"(d1), "+f"(d2), "+f"(d3)
        : "r"(A0), "r"(A1), "r"(A2), "r"(A3), "r"(B0), "r"(B1));
}

// ---------------- init -------------------------------------------------------
__global__ void init_kernel() {
    int i = blockIdx.x * blockDim.x + threadIdx.x;
    if (i < B_*S_) d_rowof[i] = -1;
    if (i < B_)    d_cnt[i]   = 0;
    if (i == 0)    d_confsum  = 0.0f;
}

// ---------------- per-row dual dot (topk score + gate logit), fp32 exact -----
__global__ void rowdot2_kernel(const float* __restrict__ X,
                               const float* __restrict__ w1,
                               const float* __restrict__ b1,
                               const float* __restrict__ w2,
                               const float* __restrict__ b2,
                               float* __restrict__ out1,
                               float* __restrict__ out2,
                               int nrows, int dim) {
    int warp = (blockIdx.x * blockDim.x + threadIdx.x) >> 5;
    int lane = threadIdx.x & 31;
    if (warp >= nrows) return;
    const float4* x4  = (const float4*)(X + (long)warp * dim);
    const float4* w14 = (const float4*)w1;
    const float4* w24 = (const float4*)w2;
    float s1 = 0.0f, s2 = 0.0f;
    for (int i = lane; i < dim / 4; i += 32) {
        float4 a = x4[i];
        float4 u = w14[i];
        float4 v = w24[i];
        s1 += a.x*u.x + a.y*u.y + a.z*u.z + a.w*u.w;
        s2 += a.x*v.x + a.y*v.y + a.z*v.z + a.w*v.w;
    }
    #pragma unroll
    for (int off = 16; off; off >>= 1) {
        s1 += __shfl_xor_sync(0xffffffffu, s1, off);
        s2 += __shfl_xor_sync(0xffffffffu, s2, off);
    }
    if (lane == 0) {
        out1[warp] = s1 + b1[0];
        out2[warp] = s2 + b2[0];
    }
}

// ---------------- mean row-norm of scaf (confidence) -------------------------
__global__ void norm_kernel(const float* __restrict__ scaf) {
    int warp = (blockIdx.x * blockDim.x + threadIdx.x) >> 5;
    int lane = threadIdx.x & 31;
    if (warp >= B_*S2_) return;
    const float4* x4 = (const float4*)(scaf + (long)warp * D_);
    float s = 0.0f;
    for (int i = lane; i < D_/4; i += 32) {
        float4 a = x4[i];
        s += a.x*a.x + a.y*a.y + a.z*a.z + a.w*a.w;
    }
    #pragma unroll
    for (int off = 16; off; off >>= 1) s += __shfl_xor_sync(0xffffffffu, s, off);
    if (lane == 0) atomicAdd(&d_confsum, sqrtf(s));
}

// ---------------- exact top-K set selection via rank counting ----------------
__global__ void select_kernel() {
    __shared__ float sh[S_];
    int b = blockIdx.x;
    const float* sc = d_scores + b * S_;
    for (int i = threadIdx.x; i < S_; i += blockDim.x) sh[i] = sc[i];
    __syncthreads();
    const int NPT = S_ / 1024;       // 4
    float myv[NPT]; int mys[NPT]; int cg[NPT], ce[NPT];
    #pragma unroll
    for (int i = 0; i < NPT; i++) {
        mys[i] = threadIdx.x + i * 1024;
        myv[i] = sh[mys[i]];
        cg[i] = 0; ce[i] = 0;
    }
    for (int j = 0; j < S_; ++j) {
        float v = sh[j];
        #pragma unroll
        for (int i = 0; i < NPT; i++) {
            cg[i] += (v > myv[i]);
            ce[i] += (v == myv[i] && j < mys[i]);
        }
    }
    #pragma unroll
    for (int i = 0; i < NPT; i++) {
        if (cg[i] + ce[i] < KSEL_) {
            int pos = atomicAdd(&d_cnt[b], 1);
            d_grows[b * KSEL_ + pos]  = b * S_ + mys[i];
            d_rowof[b * S_ + mys[i]]  = b * KSEL_ + pos;
        }
    }
}

// ---------------- TF32 tensor-core GEMM: C = A @ W^T + bias ------------------
// Tile 128x128, BK=16; 8 warps, each 64x32 (4 m-tiles x 4 n-tiles of m16n8k8).
// A: [M, lda] fp32 (optionally row-gathered), W: [N, ldb] fp32, C: [M, ldc].
// smem stride 20 floats -> fragment loads (pattern 20*g + tg) conflict-free.
#define GSTRIDE 20

template <bool GATHER>
__global__ __launch_bounds__(256)
void tf32_gemm_kernel(const float* __restrict__ A, const float* __restrict__ Bm,
                      const float* __restrict__ bias, float* __restrict__ C,
                      const int* __restrict__ grows,
                      int M, int N, int Kd, int lda, int ldb, int ldc) {
    __shared__ float As[128 * GSTRIDE];
    __shared__ float Bs[128 * GSTRIDE];

    const int tid  = threadIdx.x;
    const int w    = tid >> 5, lane = tid & 31;
    const int g    = lane >> 2, tg = lane & 3;
    const int wm   = w & 1, wn = w >> 1;          // 2 x 4 warp grid
    const int bm   = blockIdx.y * 128;
    const int bn   = blockIdx.x * 128;

    float acc[4][4][4];
    #pragma unroll
    for (int i = 0; i < 4; i++)
        #pragma unroll
        for (int j = 0; j < 4; j++)
            #pragma unroll
            for (int q = 0; q < 4; q++) acc[i][j][q] = 0.0f;

    for (int k0 = 0; k0 < Kd; k0 += 16) {
        __syncthreads();
        #pragma unroll
        for (int i = 0; i < 2; i++) {
            int idx = tid + i * 256;
            int row = idx >> 2, c4 = (idx & 3) << 2;
            int m = bm + row;
            float4 av = make_float4(0.f, 0.f, 0.f, 0.f);
            if (m < M) {
                long src = GATHER ? (long)grows[m] : (long)m;
                av = *(const float4*)(A + src * (long)lda + k0 + c4);
            }
            *(float4*)(As + row * GSTRIDE + c4) = av;
            float4 bv = *(const float4*)(Bm + (long)(bn + row) * ldb + k0 + c4);
            *(float4*)(Bs + row * GSTRIDE + c4) = bv;
        }
        __syncthreads();

        #pragma unroll
        for (int ks = 0; ks < 2; ks++) {
            int kb = ks * 8;
            float af[4][4];
            #pragma unroll
            for (int mt = 0; mt < 4; mt++) {
                int rb = wm * 64 + mt * 16;
                af[mt][0] = As[(rb + g)     * GSTRIDE + kb + tg];
                af[mt][1] = As[(rb + g + 8) * GSTRIDE + kb + tg];
                af[mt][2] = As[(rb + g)     * GSTRIDE + kb + tg + 4];
                af[mt][3] = As[(rb + g + 8) * GSTRIDE + kb + tg + 4];
            }
            float bf[4][2];
            #pragma unroll
            for (int nt = 0; nt < 4; nt++) {
                int nb = wn * 32 + nt * 8;
                bf[nt][0] = Bs[(nb + g) * GSTRIDE + kb + tg];
                bf[nt][1] = Bs[(nb + g) * GSTRIDE + kb + tg + 4];
            }
            #pragma unroll
            for (int mt = 0; mt < 4; mt++)
                #pragma unroll
                for (int nt = 0; nt < 4; nt++)
                    mma_tf32(acc[mt][nt][0], acc[mt][nt][1],
                             acc[mt][nt][2], acc[mt][nt][3],
                             af[mt][0], af[mt][1], af[mt][2], af[mt][3],
                             bf[nt][0], bf[nt][1]);
        }
    }

    // epilogue
    #pragma unroll
    for (int mt = 0; mt < 4; mt++) {
        int r0 = bm + wm * 64 + mt * 16 + g;
        int r1 = r0 + 8;
        #pragma unroll
        for (int nt = 0; nt < 4; nt++) {
            int c = bn + wn * 32 + nt * 8 + 2 * tg;
            float bz0 = bias ? bias[c] : 0.f;
            float bz1 = bias ? bias[c + 1] : 0.f;
            if (r0 < M) {
                float2 v0 = make_float2(acc[mt][nt][0] + bz0, acc[mt][nt][1] + bz1);
                *(float2*)(C + (long)r0 * ldc + c) = v0;
            }
            if (r1 < M) {
                float2 v1 = make_float2(acc[mt][nt][2] + bz0, acc[mt][nt][3] + bz1);
                *(float2*)(C + (long)r1 * ldc + c) = v1;
            }
        }
    }
}

// ---------------- TF32 fused flash attention ---------------------------------
// Block: 128 q-rows of one (b,h); 256 thr = 8 warps, warp w owns rows w*16..+15.
// Q kept as mma A-fragments in registers for the whole block (scaled).
// Online softmax on C-fragments (quad shuffles). O in-place over Q.
// smem: Ks[64][132], Vs[64][136], Ps[128][68] -> strides give conflict-free
// fragment loads (patterns 4g+tg / 8tg+g / 4g+tg mod 32).
#define KS_STRIDE 132
#define VS_STRIDE 136
#define PS_STRIDE 68
#define FLASH_SMEM ((64*KS_STRIDE + 64*VS_STRIDE + 128*PS_STRIDE) * 4)

__global__ __launch_bounds__(256, 1)
void flash_tf32_kernel(float* __restrict__ qo,
                       const float* __restrict__ kbuf,
                       const float* __restrict__ vbuf) {
    const int qt = blockIdx.x, h = blockIdx.y, b = blockIdx.z;
    const int tid = threadIdx.x;
    const int w = tid >> 5, lane = tid & 31;
    const int g = lane >> 2, tg = lane & 3;
    const float scale = 0.08838834764831845f;   // 1/sqrt(128)

    extern __shared__ float sm[];
    float* Ks = sm;                         // [64][132]
    float* Vs = sm + 64 * KS_STRIDE;        // [64][136]
    float* Ps = sm + 64 * (KS_STRIDE + VS_STRIDE);  // [128][68]

    const int qrow0 = qt * 128;
    float* qbase       = qo   + (long)b * KSEL_ * D_ + (long)h * HD_;
    const float* kbase = kbuf + (long)b * S2_ * D_ + (long)h * HD_;
    const float* vbase = vbuf + (long)b * S2_ * D_ + (long)h * HD_;

    // Q fragments (held for whole kernel), pre-scaled
    const int r0g = qrow0 + w * 16 + g;
    const int r1g = r0g + 8;
    const bool v0 = r0g < KSEL_, v1 = r1g < KSEL_;
    float qf[16][4];
    {
        const float* q0 = qbase + (long)r0g * D_;
        const float* q1 = qbase + (long)r1g * D_;
        #pragma unroll
        for (int ks = 0; ks < 16; ks++) {
            int c0 = ks * 8 + tg, c1 = c0 + 4;
            qf[ks][0] = v0 ? q0[c0] * scale : 0.f;
            qf[ks][1] = v1 ? q1[c0] * scale : 0.f;
            qf[ks][2] = v0 ? q0[c1] * scale : 0.f;
            qf[ks][3] = v1 ? q1[c1] * scale : 0.f;
        }
    }

    float oacc[16][4];
    #pragma unroll
    for (int nt = 0; nt < 16; nt++)
        #pragma unroll
        for (int q = 0; q < 4; q++) oacc[nt][q] = 0.0f;
    float m0 = -1e30f, m1 = -1e30f, l0 = 0.f, l1 = 0.f;

    for (int t = 0; t < S2_ / 64; ++t) {
        __syncthreads();
        // load K/V tiles (64 x 128 each)
        for (int i = tid; i < 64 * 32; i += 256) {
            int r = i >> 5, c4 = (i & 31) << 2;
            long go = (long)(t * 64 + r) * D_ + c4;
            *(float4*)(Ks + r * KS_STRIDE + c4) = *(const float4*)(kbase + go);
            *(float4*)(Vs + r * VS_STRIDE + c4) = *(const float4*)(vbase + go);
        }
        __syncthreads();

        // ---- S = Q K^T (warp rows w*16..+15, cols 0..63) ----
        float sa[8][4];
        #pragma unroll
        for (int j = 0; j < 8; j++)
            #pragma unroll
            for (int q = 0; q < 4; q++) sa[j][q] = 0.0f;
        #pragma unroll
        for (int ks = 0; ks < 16; ks++) {
            int kb = ks * 8;
            #pragma unroll
            for (int j = 0; j < 8; j++) {
                float b0 = Ks[(j * 8 + g) * KS_STRIDE + kb + tg];
                float b1 = Ks[(j * 8 + g) * KS_STRIDE + kb + tg + 4];
                mma_tf32(sa[j][0], sa[j][1], sa[j][2], sa[j][3],
                         qf[ks][0], qf[ks][1], qf[ks][2], qf[ks][3], b0, b1);
            }
        }

        // ---- online softmax: rows (w*16+g) via (c0,c1), (w*16+g+8) via (c2,c3)
        float rm0 = -1e30f, rm1 = -1e30f;
        #pragma unroll
        for (int j = 0; j < 8; j++) {
            rm0 = fmaxf(rm0, fmaxf(sa[j][0], sa[j][1]));
            rm1 = fmaxf(rm1, fmaxf(sa[j][2], sa[j][3]));
        }
        rm0 = fmaxf(rm0, __shfl_xor_sync(0xffffffffu, rm0, 1));
        rm0 = fmaxf(rm0, __shfl_xor_sync(0xffffffffu, rm0, 2));
        rm1 = fmaxf(rm1, __shfl_xor_sync(0xffffffffu, rm1, 1));
        rm1 = fmaxf(rm1, __shfl_xor_sync(0xffffffffu, rm1, 2));
        float mn0 = fmaxf(m0, rm0), mn1 = fmaxf(m1, rm1);
        float cr0 = __expf(m0 - mn0), cr1 = __expf(m1 - mn1);
        float ps0 = 0.f, ps1 = 0.f;
        #pragma unroll
        for (int j = 0; j < 8; j++) {
            sa[j][0] = __expf(sa[j][0] - mn0);
            sa[j][1] = __expf(sa[j][1] - mn0);
            sa[j][2] = __expf(sa[j][2] - mn1);
            sa[j][3] = __expf(sa[j][3] - mn1);
            ps0 += sa[j][0] + sa[j][1];
            ps1 += sa[j][2] + sa[j][3];
        }
        ps0 += __shfl_xor_sync(0xffffffffu, ps0, 1);
        ps0 += __shfl_xor_sync(0xffffffffu, ps0, 2);
        ps1 += __shfl_xor_sync(0xffffffffu, ps1, 1);
        ps1 += __shfl_xor_sync(0xffffffffu, ps1, 2);
        l0 = l0 * cr0 + ps0;  l1 = l1 * cr1 + ps1;
        m0 = mn0;             m1 = mn1;
        #pragma unroll
        for (int nt = 0; nt < 16; nt++) {
            oacc[nt][0] *= cr0; oacc[nt][1] *= cr0;
            oacc[nt][2] *= cr1; oacc[nt][3] *= cr1;
        }

        // stage P
        int pr0 = (w * 16 + g) * PS_STRIDE;
        int pr1 = (w * 16 + g + 8) * PS_STRIDE;
        #pragma unroll
        for (int j = 0; j < 8; j++) {
            int c = j * 8 + 2 * tg;
            Ps[pr0 + c]     = sa[j][0];
            Ps[pr0 + c + 1] = sa[j][1];
            Ps[pr1 + c]     = sa[j][2];
            Ps[pr1 + c + 1] = sa[j][3];
        }
        __syncthreads();

        // ---- O += P V ----
        #pragma unroll
        for (int ks = 0; ks < 8; ks++) {
            int kb = ks * 8;
            float a0 = Ps[pr0 + kb + tg];
            float a1 = Ps[pr1 + kb + tg];
            float a2 = Ps[pr0 + kb + tg + 4];
            float a3 = Ps[pr1 + kb + tg + 4];
            #pragma unroll
            for (int nt = 0; nt < 16; nt++) {
                float b0 = Vs[(kb + tg)     * VS_STRIDE + nt * 8 + g];
                float b1 = Vs[(kb + tg + 4) * VS_STRIDE + nt * 8 + g];
                mma_tf32(oacc[nt][0], oacc[nt][1], oacc[nt][2], oacc[nt][3],
                         a0, a1, a2, a3, b0, b1);
            }
        }
    }

    // epilogue: normalize + write in-place over Q
    float i0 = 1.0f / l0, i1 = 1.0f / l1;
    #pragma unroll
    for (int nt = 0; nt < 16; nt++) {
        int c = nt * 8 + 2 * tg;
        if (v0) *(float2*)(qbase + (long)r0g * D_ + c) =
            make_float2(oacc[nt][0] * i0, oacc[nt][1] * i0);
        if (v1) *(float2*)(qbase + (long)r1g * D_ + c) =
            make_float2(oacc[nt][2] * i1, oacc[nt][3] * i1);
    }
}

// ---------------- final fuse -------------------------------------------------
__global__ void final_kernel(const float* __restrict__ base,
                             const float* __restrict__ attn,
                             const float* __restrict__ cth,
                             float* __restrict__ out) {
    int row = blockIdx.x;                       // B*S rows
    int tid = threadIdx.x;                      // 256 threads, D/4 float4
    bool ok = (d_confsum * (1.0f / (float)(B_ * S2_)) > cth[0]);
    float g  = 1.0f / (1.0f + expf(-d_gatel[row]));
    float hg = 0.5f * g;
    int ro   = d_rowof[row];
    const float4* bp = (const float4*)(base + (long)row * D_);
    const float4* ap = (ro >= 0) ? (const float4*)(attn + (long)ro * D_) : bp;
    float4* op = (float4*)(out + (long)row * D_);
    float4 x = bp[tid];
    float4 a = ap[tid];
    float4 y;
    y.x = ok ? x.x + hg * a.x : x.x;
    y.y = ok ? x.y + hg * a.y : x.y;
    y.z = ok ? x.z + hg * a.z : x.z;
    y.w = ok ? x.w + hg * a.w : x.w;
    op[tid] = y;
}

// ---------------- host orchestration -----------------------------------------
static void run_gemm(bool gather,
                     const float* A, const float* Bm, const float* bias, float* C,
                     const int* grows, int M, int N, int Kd,
                     int lda, int ldb, int ldc) {
    dim3 grid(N / 128, (M + 127) / 128, 1);
    if (gather)
        tf32_gemm_kernel<true><<<grid, 256>>>(A, Bm, bias, C, grows,
                                              M, N, Kd, lda, ldb, ldc);
    else
        tf32_gemm_kernel<false><<<grid, 256>>>(A, Bm, bias, C, grows,
                                               M, N, Kd, lda, ldb, ldc);
}

extern "C" void kernel_launch(void* const* d_in, const int* in_sizes, int n_in,
                              void* d_out, int out_size) {
    const float* base     = (const float*)d_in[0];   // (B,S,D)
    const float* scaffold = (const float*)d_in[1];   // (B,S2,SCAF_D)
    const float* spw      = (const float*)d_in[2];   // (D,SCAF_D)
    const float* spb      = (const float*)d_in[3];   // (D,)
    const float* tkw      = (const float*)d_in[4];   // (1,D)
    const float* tkb      = (const float*)d_in[5];   // (1,)
    const float* ipw      = (const float*)d_in[6];   // (3D,D)
    const float* ipb      = (const float*)d_in[7];   // (3D,)
    const float* opw      = (const float*)d_in[8];   // (D,D)
    const float* opb      = (const float*)d_in[9];   // (D,)
    const float* gw       = (const float*)d_in[10];  // (1,D)
    const float* gb       = (const float*)d_in[11];  // (1,)
    const float* cth      = (const float*)d_in[12];  // (1,)
    float* out            = (float*)d_out;

    float* p_ws;
    float* p_scores; float* p_gatel; int* p_grows;
    cudaGetSymbolAddress((void**)&p_ws,     d_ws);
    cudaGetSymbolAddress((void**)&p_scores, d_scores);
    cudaGetSymbolAddress((void**)&p_gatel,  d_gatel);
    cudaGetSymbolAddress((void**)&p_grows,  d_grows);

    float* p_k    = p_ws + WS_K;
    float* p_v    = p_ws + WS_V;
    float* p_attn = p_ws + WS_ATTN;
    float* p_scaf = out;               // scaf staged in d_out (dead before q)
    float* p_qo   = out;               // q, then o in-place; dead before final

    cudaFuncSetAttribute(flash_tf32_kernel,
                         cudaFuncAttributeMaxDynamicSharedMemorySize, FLASH_SMEM);

    // 1) init small state
    init_kernel<<<64, 256>>>();

    // 2) fp32-exact topk scores + gate logits in one pass over base
    rowdot2_kernel<<<(B_ * S_ * 32 + 255) / 256, 256>>>(
        base, tkw, tkb, gw, gb, p_scores, p_gatel, B_ * S_, D_);

    // 3) exact top-K set per batch
    select_kernel<<<B_, 1024>>>();

    // 4) scaf = scaffold @ spw^T + spb  (8192 x 1024 x 768) -> d_out
    run_gemm(false, scaffold, spw, spb, p_scaf, nullptr,
             B_ * S2_, D_, SCAFD_, SCAFD_, SCAFD_, D_);

    // 5) confidence = mean row norm of scaf
    norm_kernel<<<(B_ * S2_ * 32 + 255) / 256, 256>>>(p_scaf);

    // 6) k = scaf @ wk^T + bk ; v = scaf @ wv^T + bv  -> d_ws
    run_gemm(false, p_scaf, ipw + (long)D_ * D_, ipb + D_, p_k, nullptr,
             B_ * S2_, D_, D_, D_, D_, D_);
    run_gemm(false, p_scaf, ipw + 2L * D_ * D_, ipb + 2 * D_, p_v, nullptr,
             B_ * S2_, D_, D_, D_, D_, D_);

    // 7) q = gather(base) @ wq^T + bq  (10196 x 1024 x 1024) -> d_out
    run_gemm(true, base, ipw, ipb, p_qo, p_grows,
             BKROWS_, D_, D_, D_, D_, D_);

    // 8) fused flash attention (tf32 mma); o overwrites q in-place
    {
        dim3 grid((KSEL_ + 127) / 128, H_, B_);
        flash_tf32_kernel<<<grid, 256, FLASH_SMEM>>>(p_qo, p_k, p_v);
    }

    // 9) attn_out = o @ opw^T + opb -> d_ws (overlays dead k/v head)
    run_gemm(false, p_qo, opw, opb, p_attn, nullptr,
             BKROWS_, D_, D_, D_, D_, D_);

    // 10) fuse (rewrites all of d_out; o dead)
    final_kernel<<<B_ * S_, 256>>>(base, p_attn, cth, out);
}

// round 10
// speedup vs baseline: 2.9948x; 1.0001x over previous
#include <cuda_runtime.h>
#include <math.h>
#include <stdint.h>

#define B_      4
#define S_      4096
#define S2_     2048
#define D_      1024
#define SCAFD_  768
#define H_      8
#define HD_     128
#define KSEL_   2549                 // int(4096 * sigmoid(0.5))
#define BKROWS_ (B_*KSEL_)           // 10196

// ---------------- scratch ----------------------------------------------------
//   d_ws layout (floats):
//     [0,        8388608)  k        (live: qkv GEMM .. flash)
//     [8388608, 16777216)  v        (live: qkv GEMM .. flash)
//     [0,       10440704)  attn_out (live: attn GEMM .. final; k/v dead then)
#define WS_K    0L
#define WS_V    8388608L
#define WS_ATTN 0L
__device__ float d_ws[16777216];     // 67.1 MB
__device__ float d_scores[B_*S_];
__device__ float d_gatel [B_*S_];
__device__ int   d_grows [BKROWS_];
__device__ int   d_rowof [B_*S_];
__device__ int   d_cnt   [B_];
__device__ float d_confsum;

// ---------------- tf32 mma helper --------------------------------------------
__device__ __forceinline__ void mma_tf32(float& d0, float& d1, float& d2, float& d3,
                                         float a0, float a1, float a2, float a3,
                                         float b0, float b1) {
    uint32_t A0 = __float_as_uint(a0), A1 = __float_as_uint(a1);
    uint32_t A2 = __float_as_uint(a2), A3 = __float_as_uint(a3);
    uint32_t B0 = __float_as_uint(b0), B1 = __float_as_uint(b1);
    asm volatile(
        "mma.sync.aligned.m16n8k8.row.col.f32.tf32.tf32.f32 "
        "{%0,%1,%2,%3}, {%4,%5,%6,%7}, {%8,%9}, {%0,%1,%2,%3};"
        : "+f"(d0), "+f"(d1), "+f"(d2), "+f"(d3)
        : "r"(A0), "r"(A1), "r"(A2), "r"(A3), "r"(B0), "r"(B1));
}

// ---------------- init -------------------------------------------------------
__global__ void init_kernel() {
    int i = blockIdx.x * blockDim.x + threadIdx.x;
    if (i < B_*S_) d_rowof[i] = -1;
    if (i < B_)    d_cnt[i]   = 0;
    if (i == 0)    d_confsum  = 0.0f;
}

// ---------------- per-row dual dot (topk score + gate logit), fp32 exact -----
__global__ void rowdot2_kernel(const float* __restrict__ X,
                               const float* __restrict__ w1,
                               const float* __restrict__ b1,
                               const float* __restrict__ w2,
                               const float* __restrict__ b2,
                               float* __restrict__ out1,
                               float* __restrict__ out2,
                               int nrows, int dim) {
    int warp = (blockIdx.x * blockDim.x + threadIdx.x) >> 5;
    int lane = threadIdx.x & 31;
    if (warp >= nrows) return;
    const float4* x4  = (const float4*)(X + (long)warp * dim);
    const float4* w14 = (const float4*)w1;
    const float4* w24 = (const float4*)w2;
    float s1 = 0.0f, s2 = 0.0f;
    for (int i = lane; i < dim / 4; i += 32) {
        float4 a = x4[i];
        float4 u = w14[i];
        float4 v = w24[i];
        s1 += a.x*u.x + a.y*u.y + a.z*u.z + a.w*u.w;
        s2 += a.x*v.x + a.y*v.y + a.z*v.z + a.w*v.w;
    }
    #pragma unroll
    for (int off = 16; off; off >>= 1) {
        s1 += __shfl_xor_sync(0xffffffffu, s1, off);
        s2 += __shfl_xor_sync(0xffffffffu, s2, off);
    }
    if (lane == 0) {
        out1[warp] = s1 + b1[0];
        out2[warp] = s2 + b2[0];
    }
}

// ---------------- mean row-norm of scaf (confidence) -------------------------
__global__ void norm_kernel(const float* __restrict__ scaf) {
    int warp = (blockIdx.x * blockDim.x + threadIdx.x) >> 5;
    int lane = threadIdx.x & 31;
    if (warp >= B_*S2_) return;
    const float4* x4 = (const float4*)(scaf + (long)warp * D_);
    float s = 0.0f;
    for (int i = lane; i < D_/4; i += 32) {
        float4 a = x4[i];
        s += a.x*a.x + a.y*a.y + a.z*a.z + a.w*a.w;
    }
    #pragma unroll
    for (int off = 16; off; off >>= 1) s += __shfl_xor_sync(0xffffffffu, s, off);
    if (lane == 0) atomicAdd(&d_confsum, sqrtf(s));
}

// ---------------- exact top-K set selection via rank counting ----------------
__global__ void select_kernel() {
    __shared__ float sh[S_];
    int b = blockIdx.x;
    const float* sc = d_scores + b * S_;
    for (int i = threadIdx.x; i < S_; i += blockDim.x) sh[i] = sc[i];
    __syncthreads();
    const int NPT = S_ / 1024;       // 4
    float myv[NPT]; int mys[NPT]; int cg[NPT], ce[NPT];
    #pragma unroll
    for (int i = 0; i < NPT; i++) {
        mys[i] = threadIdx.x + i * 1024;
        myv[i] = sh[mys[i]];
        cg[i] = 0; ce[i] = 0;
    }
    for (int j = 0; j < S_; ++j) {
        float v = sh[j];
        #pragma unroll
        for (int i = 0; i < NPT; i++) {
            cg[i] += (v > myv[i]);
            ce[i] += (v == myv[i] && j < mys[i]);
        }
    }
    #pragma unroll
    for (int i = 0; i < NPT; i++) {
        if (cg[i] + ce[i] < KSEL_) {
            int pos = atomicAdd(&d_cnt[b], 1);
            d_grows[b * KSEL_ + pos]  = b * S_ + mys[i];
            d_rowof[b * S_ + mys[i]]  = b * KSEL_ + pos;
        }
    }
}

// ---------------- TF32 tensor-core GEMM: C = A @ W^T + bias ------------------
// Tile 128x128, BK=16; 8 warps, each 64x32 (4 m-tiles x 4 n-tiles of m16n8k8).
// A: [M, lda] fp32 (optionally row-gathered), W: [N, ldb] fp32, C: [M, ldc].
// smem stride 20 floats -> fragment loads (pattern 20*g + tg) conflict-free.
#define GSTRIDE 20

template <bool GATHER>
__global__ __launch_bounds__(256)
void tf32_gemm_kernel(const float* __restrict__ A, const float* __restrict__ Bm,
                      const float* __restrict__ bias, float* __restrict__ C,
                      const int* __restrict__ grows,
                      int M, int N, int Kd, int lda, int ldb, int ldc) {
    __shared__ float As[128 * GSTRIDE];
    __shared__ float Bs[128 * GSTRIDE];

    const int tid  = threadIdx.x;
    const int w    = tid >> 5, lane = tid & 31;
    const int g    = lane >> 2, tg = lane & 3;
    const int wm   = w & 1, wn = w >> 1;          // 2 x 4 warp grid
    const int bm   = blockIdx.y * 128;
    const int bn   = blockIdx.x * 128;

    float acc[4][4][4];
    #pragma unroll
    for (int i = 0; i < 4; i++)
        #pragma unroll
        for (int j = 0; j < 4; j++)
            #pragma unroll
            for (int q = 0; q < 4; q++) acc[i][j][q] = 0.0f;

    for (int k0 = 0; k0 < Kd; k0 += 16) {
        __syncthreads();
        #pragma unroll
        for (int i = 0; i < 2; i++) {
            int idx = tid + i * 256;
            int row = idx >> 2, c4 = (idx & 3) << 2;
            int m = bm + row;
            float4 av = make_float4(0.f, 0.f, 0.f, 0.f);
            if (m < M) {
                long src = GATHER ? (long)grows[m] : (long)m;
                av = *(const float4*)(A + src * (long)lda + k0 + c4);
            }
            *(float4*)(As + row * GSTRIDE + c4) = av;
            float4 bv = *(const float4*)(Bm + (long)(bn + row) * ldb + k0 + c4);
            *(float4*)(Bs + row * GSTRIDE + c4) = bv;
        }
        __syncthreads();

        #pragma unroll
        for (int ks = 0; ks < 2; ks++) {
            int kb = ks * 8;
            float af[4][4];
            #pragma unroll
            for (int mt = 0; mt < 4; mt++) {
                int rb = wm * 64 + mt * 16;
                af[mt][0] = As[(rb + g)     * GSTRIDE + kb + tg];
                af[mt][1] = As[(rb + g + 8) * GSTRIDE + kb + tg];
                af[mt][2] = As[(rb + g)     * GSTRIDE + kb + tg + 4];
                af[mt][3] = As[(rb + g + 8) * GSTRIDE + kb + tg + 4];
            }
            float bf[4][2];
            #pragma unroll
            for (int nt = 0; nt < 4; nt++) {
                int nb = wn * 32 + nt * 8;
                bf[nt][0] = Bs[(nb + g) * GSTRIDE + kb + tg];
                bf[nt][1] = Bs[(nb + g) * GSTRIDE + kb + tg + 4];
            }
            #pragma unroll
            for (int mt = 0; mt < 4; mt++)
                #pragma unroll
                for (int nt = 0; nt < 4; nt++)
                    mma_tf32(acc[mt][nt][0], acc[mt][nt][1],
                             acc[mt][nt][2], acc[mt][nt][3],
                             af[mt][0], af[mt][1], af[mt][2], af[mt][3],
                             bf[nt][0], bf[nt][1]);
        }
    }

    // epilogue
    #pragma unroll
    for (int mt = 0; mt < 4; mt++) {
        int r0 = bm + wm * 64 + mt * 16 + g;
        int r1 = r0 + 8;
        #pragma unroll
        for (int nt = 0; nt < 4; nt++) {
            int c = bn + wn * 32 + nt * 8 + 2 * tg;
            float bz0 = bias ? bias[c] : 0.f;
            float bz1 = bias ? bias[c + 1] : 0.f;
            if (r0 < M) {
                float2 v0 = make_float2(acc[mt][nt][0] + bz0, acc[mt][nt][1] + bz1);
                *(float2*)(C + (long)r0 * ldc + c) = v0;
            }
            if (r1 < M) {
                float2 v1 = make_float2(acc[mt][nt][2] + bz0, acc[mt][nt][3] + bz1);
                *(float2*)(C + (long)r1 * ldc + c) = v1;
            }
        }
    }
}

// ---------------- TF32 fused flash attention ---------------------------------
// Block: 128 q-rows of one (b,h); 256 thr = 8 warps, warp w owns rows w*16..+15.
// Q kept as mma A-fragments in registers for the whole block (scaled).
// Online softmax on C-fragments (quad shuffles). O in-place over Q.
// smem: Ks[64][132], Vs[64][136], Ps[128][68] -> strides give conflict-free
// fragment loads (patterns 4g+tg / 8tg+g / 4g+tg mod 32).
#define KS_STRIDE 132
#define VS_STRIDE 136
#define PS_STRIDE 68
#define FLASH_SMEM ((64*KS_STRIDE + 64*VS_STRIDE + 128*PS_STRIDE) * 4)

__global__ __launch_bounds__(256, 1)
void flash_tf32_kernel(float* __restrict__ qo,
                       const float* __restrict__ kbuf,
                       const float* __restrict__ vbuf) {
    const int qt = blockIdx.x, h = blockIdx.y, b = blockIdx.z;
    const int tid = threadIdx.x;
    const int w = tid >> 5, lane = tid & 31;
    const int g = lane >> 2, tg = lane & 3;
    const float scale = 0.08838834764831845f;   // 1/sqrt(128)

    extern __shared__ float sm[];
    float* Ks = sm;                         // [64][132]
    float* Vs = sm + 64 * KS_STRIDE;        // [64][136]
    float* Ps = sm + 64 * (KS_STRIDE + VS_STRIDE);  // [128][68]

    const int qrow0 = qt * 128;
    float* qbase       = qo   + (long)b * KSEL_ * D_ + (long)h * HD_;
    const float* kbase = kbuf + (long)b * S2_ * D_ + (long)h * HD_;
    const float* vbase = vbuf + (long)b * S2_ * D_ + (long)h * HD_;

    // Q fragments (held for whole kernel), pre-scaled
    const int r0g = qrow0 + w * 16 + g;
    const int r1g = r0g + 8;
    const bool v0 = r0g < KSEL_, v1 = r1g < KSEL_;
    float qf[16][4];
    {
        const float* q0 = qbase + (long)r0g * D_;
        const float* q1 = qbase + (long)r1g * D_;
        #pragma unroll
        for (int ks = 0; ks < 16; ks++) {
            int c0 = ks * 8 + tg, c1 = c0 + 4;
            qf[ks][0] = v0 ? q0[c0] * scale : 0.f;
            qf[ks][1] = v1 ? q1[c0] * scale : 0.f;
            qf[ks][2] = v0 ? q0[c1] * scale : 0.f;
            qf[ks][3] = v1 ? q1[c1] * scale : 0.f;
        }
    }

    float oacc[16][4];
    #pragma unroll
    for (int nt = 0; nt < 16; nt++)
        #pragma unroll
        for (int q = 0; q < 4; q++) oacc[nt][q] = 0.0f;
    float m0 = -1e30f, m1 = -1e30f, l0 = 0.f, l1 = 0.f;

    for (int t = 0; t < S2_ / 64; ++t) {
        __syncthreads();
        // load K/V tiles (64 x 128 each)
        for (int i = tid; i < 64 * 32; i += 256) {
            int r = i >> 5, c4 = (i & 31) << 2;
            long go = (long)(t * 64 + r) * D_ + c4;
            *(float4*)(Ks + r * KS_STRIDE + c4) = *(const float4*)(kbase + go);
            *(float4*)(Vs + r * VS_STRIDE + c4) = *(const float4*)(vbase + go);
        }
        __syncthreads();

        // ---- S = Q K^T (warp rows w*16..+15, cols 0..63) ----
        float sa[8][4];
        #pragma unroll
        for (int j = 0; j < 8; j++)
            #pragma unroll
            for (int q = 0; q < 4; q++) sa[j][q] = 0.0f;
        #pragma unroll
        for (int ks = 0; ks < 16; ks++) {
            int kb = ks * 8;
            #pragma unroll
            for (int j = 0; j < 8; j++) {
                float b0 = Ks[(j * 8 + g) * KS_STRIDE + kb + tg];
                float b1 = Ks[(j * 8 + g) * KS_STRIDE + kb + tg + 4];
                mma_tf32(sa[j][0], sa[j][1], sa[j][2], sa[j][3],
                         qf[ks][0], qf[ks][1], qf[ks][2], qf[ks][3], b0, b1);
            }
        }

        // ---- online softmax: rows (w*16+g) via (c0,c1), (w*16+g+8) via (c2,c3)
        float rm0 = -1e30f, rm1 = -1e30f;
        #pragma unroll
        for (int j = 0; j < 8; j++) {
            rm0 = fmaxf(rm0, fmaxf(sa[j][0], sa[j][1]));
            rm1 = fmaxf(rm1, fmaxf(sa[j][2], sa[j][3]));
        }
        rm0 = fmaxf(rm0, __shfl_xor_sync(0xffffffffu, rm0, 1));
        rm0 = fmaxf(rm0, __shfl_xor_sync(0xffffffffu, rm0, 2));
        rm1 = fmaxf(rm1, __shfl_xor_sync(0xffffffffu, rm1, 1));
        rm1 = fmaxf(rm1, __shfl_xor_sync(0xffffffffu, rm1, 2));
        float mn0 = fmaxf(m0, rm0), mn1 = fmaxf(m1, rm1);
        float cr0 = __expf(m0 - mn0), cr1 = __expf(m1 - mn1);
        float ps0 = 0.f, ps1 = 0.f;
        #pragma unroll
        for (int j = 0; j < 8; j++) {
            sa[j][0] = __expf(sa[j][0] - mn0);
            sa[j][1] = __expf(sa[j][1] - mn0);
            sa[j][2] = __expf(sa[j][2] - mn1);
            sa[j][3] = __expf(sa[j][3] - mn1);
            ps0 += sa[j][0] + sa[j][1];
            ps1 += sa[j][2] + sa[j][3];
        }
        ps0 += __shfl_xor_sync(0xffffffffu, ps0, 1);
        ps0 += __shfl_xor_sync(0xffffffffu, ps0, 2);
        ps1 += __shfl_xor_sync(0xffffffffu, ps1, 1);
        ps1 += __shfl_xor_sync(0xffffffffu, ps1, 2);
        l0 = l0 * cr0 + ps0;  l1 = l1 * cr1 + ps1;
        m0 = mn0;             m1 = mn1;
        #pragma unroll
        for (int nt = 0; nt < 16; nt++) {
            oacc[nt][0] *= cr0; oacc[nt][1] *= cr0;
            oacc[nt][2] *= cr1; oacc[nt][3] *= cr1;
        }

        // stage P
        int pr0 = (w * 16 + g) * PS_STRIDE;
        int pr1 = (w * 16 + g + 8) * PS_STRIDE;
        #pragma unroll
        for (int j = 0; j < 8; j++) {
            int c = j * 8 + 2 * tg;
            Ps[pr0 + c]     = sa[j][0];
            Ps[pr0 + c + 1] = sa[j][1];
            Ps[pr1 + c]     = sa[j][2];
            Ps[pr1 + c + 1] = sa[j][3];
        }
        __syncthreads();

        // ---- O += P V ----
        #pragma unroll
        for (int ks = 0; ks < 8; ks++) {
            int kb = ks * 8;
            float a0 = Ps[pr0 + kb + tg];
            float a1 = Ps[pr1 + kb + tg];
            float a2 = Ps[pr0 + kb + tg + 4];
            float a3 = Ps[pr1 + kb + tg + 4];
            #pragma unroll
            for (int nt = 0; nt < 16; nt++) {
                float b0 = Vs[(kb + tg)     * VS_STRIDE + nt * 8 + g];
                float b1 = Vs[(kb + tg + 4) * VS_STRIDE + nt * 8 + g];
                mma_tf32(oacc[nt][0], oacc[nt][1], oacc[nt][2], oacc[nt][3],
                         a0, a1, a2, a3, b0, b1);
            }
        }
    }

    // epilogue: normalize + write in-place over Q
    float i0 = 1.0f / l0, i1 = 1.0f / l1;
    #pragma unroll
    for (int nt = 0; nt < 16; nt++) {
        int c = nt * 8 + 2 * tg;
        if (v0) *(float2*)(qbase + (long)r0g * D_ + c) =
            make_float2(oacc[nt][0] * i0, oacc[nt][1] * i0);
        if (v1) *(float2*)(qbase + (long)r1g * D_ + c) =
            make_float2(oacc[nt][2] * i1, oacc[nt][3] * i1);
    }
}

// ---------------- final fuse -------------------------------------------------
__global__ void final_kernel(const float* __restrict__ base,
                             const float* __restrict__ attn,
                             const float* __restrict__ cth,
                             float* __restrict__ out) {
    int row = blockIdx.x;                       // B*S rows
    int tid = threadIdx.x;                      // 256 threads, D/4 float4
    bool ok = (d_confsum * (1.0f / (float)(B_ * S2_)) > cth[0]);
    float g  = 1.0f / (1.0f + expf(-d_gatel[row]));
    float hg = 0.5f * g;
    int ro   = d_rowof[row];
    const float4* bp = (const float4*)(base + (long)row * D_);
    const float4* ap = (ro >= 0) ? (const float4*)(attn + (long)ro * D_) : bp;
    float4* op = (float4*)(out + (long)row * D_);
    float4 x = bp[tid];
    float4 a = ap[tid];
    float4 y;
    y.x = ok ? x.x + hg * a.x : x.x;
    y.y = ok ? x.y + hg * a.y : x.y;
    y.z = ok ? x.z + hg * a.z : x.z;
    y.w = ok ? x.w + hg * a.w : x.w;
    op[tid] = y;
}

// ---------------- host orchestration -----------------------------------------
static void run_gemm(bool gather,
                     const float* A, const float* Bm, const float* bias, float* C,
                     const int* grows, int M, int N, int Kd,
                     int lda, int ldb, int ldc) {
    dim3 grid(N / 128, (M + 127) / 128, 1);
    if (gather)
        tf32_gemm_kernel<true><<<grid, 256>>>(A, Bm, bias, C, grows,
                                              M, N, Kd, lda, ldb, ldc);
    else
        tf32_gemm_kernel<false><<<grid, 256>>>(A, Bm, bias, C, grows,
                                               M, N, Kd, lda, ldb, ldc);
}

extern "C" void kernel_launch(void* const* d_in, const int* in_sizes, int n_in,
                              void* d_out, int out_size) {
    const float* base     = (const float*)d_in[0];   // (B,S,D)
    const float* scaffold = (const float*)d_in[1];   // (B,S2,SCAF_D)
    const float* spw      = (const float*)d_in[2];   // (D,SCAF_D)
    const float* spb      = (const float*)d_in[3];   // (D,)
    const float* tkw      = (const float*)d_in[4];   // (1,D)
    const float* tkb      = (const float*)d_in[5];   // (1,)
    const float* ipw      = (const float*)d_in[6];   // (3D,D)
    const float* ipb      = (const float*)d_in[7];   // (3D,)
    const float* opw      = (const float*)d_in[8];   // (D,D)
    const float* opb      = (const float*)d_in[9];   // (D,)
    const float* gw       = (const float*)d_in[10];  // (1,D)
    const float* gb       = (const float*)d_in[11];  // (1,)
    const float* cth      = (const float*)d_in[12];  // (1,)
    float* out            = (float*)d_out;

    float* p_ws;
    float* p_scores; float* p_gatel; int* p_grows;
    cudaGetSymbolAddress((void**)&p_ws,     d_ws);
    cudaGetSymbolAddress((void**)&p_scores, d_scores);
    cudaGetSymbolAddress((void**)&p_gatel,  d_gatel);
    cudaGetSymbolAddress((void**)&p_grows,  d_grows);

    float* p_k    = p_ws + WS_K;
    float* p_v    = p_ws + WS_V;
    float* p_attn = p_ws + WS_ATTN;
    float* p_scaf = out;               // scaf staged in d_out (dead before q)
    float* p_qo   = out;               // q, then o in-place; dead before final

    cudaFuncSetAttribute(flash_tf32_kernel,
                         cudaFuncAttributeMaxDynamicSharedMemorySize, FLASH_SMEM);

    // 1) init small state
    init_kernel<<<64, 256>>>();

    // 2) fp32-exact topk scores + gate logits in one pass over base
    rowdot2_kernel<<<(B_ * S_ * 32 + 255) / 256, 256>>>(
        base, tkw, tkb, gw, gb, p_scores, p_gatel, B_ * S_, D_);

    // 3) exact top-K set per batch
    select_kernel<<<B_, 1024>>>();

    // 4) scaf = scaffold @ spw^T + spb  (8192 x 1024 x 768) -> d_out
    run_gemm(false, scaffold, spw, spb, p_scaf, nullptr,
             B_ * S2_, D_, SCAFD_, SCAFD_, SCAFD_, D_);

    // 5) confidence = mean row norm of scaf
    norm_kernel<<<(B_ * S2_ * 32 + 255) / 256, 256>>>(p_scaf);

    // 6) k = scaf @ wk^T + bk ; v = scaf @ wv^T + bv  -> d_ws
    run_gemm(false, p_scaf, ipw + (long)D_ * D_, ipb + D_, p_k, nullptr,
             B_ * S2_, D_, D_, D_, D_, D_);
    run_gemm(false, p_scaf, ipw + 2L * D_ * D_, ipb + 2 * D_, p_v, nullptr,
             B_ * S2_, D_, D_, D_, D_, D_);

    // 7) q = gather(base) @ wq^T + bq  (10196 x 1024 x 1024) -> d_out
    run_gemm(true, base, ipw, ipb, p_qo, p_grows,
             BKROWS_, D_, D_, D_, D_, D_);

    // 8) fused flash attention (tf32 mma); o overwrites q in-place
    {
        dim3 grid((KSEL_ + 127) / 128, H_, B_);
        flash_tf32_kernel<<<grid, 256, FLASH_SMEM>>>(p_qo, p_k, p_v);
    }

    // 9) attn_out = o @ opw^T + opb -> d_ws (overlays dead k/v head)
    run_gemm(false, p_qo, opw, opb, p_attn, nullptr,
             BKROWS_, D_, D_, D_, D_, D_);

    // 10) fuse (rewrites all of d_out; o dead)
    final_kernel<<<B_ * S_, 256>>>(base, p_attn, cth, out);
}

// round 13
// speedup vs baseline: 4.4282x; 1.4787x over previous
#include <cuda_runtime.h>
#include <math.h>
#include <stdint.h>

#define B_      4
#define S_      4096
#define S2_     2048
#define D_      1024
#define SCAFD_  768
#define H_      8
#define HD_     128
#define KSEL_   2549
#define BKROWS_ (B_*KSEL_)           // 10196

// ---------------- scratch ----------------------------------------------------
// d_ws: k [0,8388608) v [8388608,16777216) live until flash; attn fp32
// [0,10440704) overlays them after (k/v dead).
#define WS_K    0L
#define WS_V    8388608L
#define WS_ATTN 0L
__device__ float d_ws[16777216];     // 67.1 MB
__device__ float d_scores[B_*S_];
__device__ float d_gatel [B_*S_];
__device__ int   d_grows [BKROWS_];
__device__ int   d_rowof [B_*S_];
__device__ int   d_cnt   [B_];
__device__ float d_confsum;

// ---------------- helpers ----------------------------------------------------
__device__ __forceinline__ uint32_t smem_u32(const void* p) {
    return (uint32_t)__cvta_generic_to_shared(p);
}
__device__ __forceinline__ void cp16(uint32_t s, const void* g, bool v) {
    asm volatile("cp.async.cg.shared.global [%0], [%1], 16, %2;"
                 :: "r"(s), "l"(g), "r"(v ? 16 : 0));
}
#define CP_COMMIT() asm volatile("cp.async.commit_group;")
#define CP_WAIT0()  asm volatile("cp.async.wait_group 0;")

__device__ __forceinline__ void mma_tf32(float& d0, float& d1, float& d2, float& d3,
                                         float a0, float a1, float a2, float a3,
                                         float b0, float b1) {
    uint32_t A0 = __float_as_uint(a0), A1 = __float_as_uint(a1);
    uint32_t A2 = __float_as_uint(a2), A3 = __float_as_uint(a3);
    uint32_t B0 = __float_as_uint(b0), B1 = __float_as_uint(b1);
    asm volatile(
        "mma.sync.aligned.m16n8k8.row.col.f32.tf32.tf32.f32 "
        "{%0,%1,%2,%3}, {%4,%5,%6,%7}, {%8,%9}, {%0,%1,%2,%3};"
        : "+f"(d0), "+f"(d1), "+f"(d2), "+f"(d3)
        : "r"(A0), "r"(A1), "r"(A2), "r"(A3), "r"(B0), "r"(B1));
}

// ---------------- init -------------------------------------------------------
__global__ void init_kernel() {
    int i = blockIdx.x * blockDim.x + threadIdx.x;
    if (i < B_*S_) d_rowof[i] = -1;
    if (i < B_)    d_cnt[i]   = 0;
    if (i == 0)    d_confsum  = 0.0f;
}

// ---------------- exact fp32 dual row-dot ------------------------------------
__global__ void rowdot2_kernel(const float* __restrict__ X,
                               const float* __restrict__ w1, const float* __restrict__ b1,
                               const float* __restrict__ w2, const float* __restrict__ b2,
                               float* __restrict__ o1, float* __restrict__ o2, int nrows) {
    int warp = (blockIdx.x * blockDim.x + threadIdx.x) >> 5;
    int lane = threadIdx.x & 31;
    if (warp >= nrows) return;
    const float4* x4 = (const float4*)(X + (long)warp * D_);
    const float4* u4 = (const float4*)w1;
    const float4* v4 = (const float4*)w2;
    float s1 = 0.f, s2 = 0.f;
    for (int i = lane; i < D_/4; i += 32) {
        float4 a = x4[i], u = u4[i], v = v4[i];
        s1 += a.x*u.x + a.y*u.y + a.z*u.z + a.w*u.w;
        s2 += a.x*v.x + a.y*v.y + a.z*v.z + a.w*v.w;
    }
    #pragma unroll
    for (int off = 16; off; off >>= 1) {
        s1 += __shfl_xor_sync(0xffffffffu, s1, off);
        s2 += __shfl_xor_sync(0xffffffffu, s2, off);
    }
    if (lane == 0) { o1[warp] = s1 + b1[0]; o2[warp] = s2 + b2[0]; }
}

// ---------------- mean row-norm of scaf --------------------------------------
__global__ void norm_kernel(const float* __restrict__ scaf) {
    int warp = (blockIdx.x * blockDim.x + threadIdx.x) >> 5;
    int lane = threadIdx.x & 31;
    if (warp >= B_*S2_) return;
    const float4* x4 = (const float4*)(scaf + (long)warp * D_);
    float s = 0.f;
    for (int i = lane; i < D_/4; i += 32) {
        float4 a = x4[i];
        s += a.x*a.x + a.y*a.y + a.z*a.z + a.w*a.w;
    }
    #pragma unroll
    for (int off = 16; off; off >>= 1) s += __shfl_xor_sync(0xffffffffu, s, off);
    if (lane == 0) atomicAdd(&d_confsum, sqrtf(s));
}

// ---------------- exact top-K via rank counting (parallel over candidates) ---
__global__ void select_kernel() {
    __shared__ float sh[S_];
    int b = blockIdx.y;
    const float* sc = d_scores + b * S_;
    for (int i = threadIdx.x; i < S_; i += 256) sh[i] = sc[i];
    __syncthreads();
    int cand = blockIdx.x * 256 + threadIdx.x;
    float myv = sh[cand];
    int cnt = 0;
    for (int j = 0; j < S_; j += 4) {
        float4 v = *(const float4*)&sh[j];
        cnt += (v.x > myv) || (v.x == myv && (j + 0) < cand);
        cnt += (v.y > myv) || (v.y == myv && (j + 1) < cand);
        cnt += (v.z > myv) || (v.z == myv && (j + 2) < cand);
        cnt += (v.w > myv) || (v.w == myv && (j + 3) < cand);
    }
    if (cnt < KSEL_) {
        int pos = atomicAdd(&d_cnt[b], 1);
        d_grows[b * KSEL_ + pos] = b * S_ + cand;
        d_rowof[b * S_ + cand]   = b * KSEL_ + pos;
    }
}

// ---------------- TF32 GEMM, cp.async double-buffered ------------------------
// 128x128 tile, BK=16, 8 warps (2m x 4n), each 64x32 via m16n8k8.
#define GSTRIDE 20
#define STG_B   (128 * GSTRIDE * 4)

template <bool GATHER>
__global__ __launch_bounds__(256)
void tf32_gemm_kernel(const float* __restrict__ A, const float* __restrict__ Bm,
                      const float* __restrict__ bias, float* __restrict__ C,
                      const int* __restrict__ grows,
                      int M, int N, int Kd, int lda, int ldb, int ldc) {
    __shared__ float As[2][128 * GSTRIDE];
    __shared__ float Bs[2][128 * GSTRIDE];

    const int tid  = threadIdx.x;
    const int w    = tid >> 5, lane = tid & 31;
    const int g    = lane >> 2, tg = lane & 3;
    const int wm   = w & 1, wn = w >> 1;
    const int bm   = blockIdx.y * 128;
    const int bn   = blockIdx.x * 128;

    // copy map: 2 chunks per thread per matrix
    int crow[2], cc4[2]; bool av[2];
    const float* agp[2]; const float* bgp[2];
    uint32_t daA[2], daB[2];
    uint32_t sa0 = smem_u32(&As[0][0]), sb0 = smem_u32(&Bs[0][0]);
    #pragma unroll
    for (int i = 0; i < 2; i++) {
        int idx = tid + i * 256;
        crow[i] = idx >> 2; cc4[i] = (idx & 3) << 2;
        av[i] = (bm + crow[i]) < M;
        long arow = av[i] ? (GATHER ? (long)grows[bm + crow[i]]
                                    : (long)(bm + crow[i])) : 0;
        agp[i] = A + arow * (long)lda;
        bgp[i] = Bm + (long)(bn + crow[i]) * ldb;
        daA[i] = sa0 + (crow[i] * GSTRIDE + cc4[i]) * 4;
        daB[i] = sb0 + (crow[i] * GSTRIDE + cc4[i]) * 4;
    }

    float acc[4][4][4];
    #pragma unroll
    for (int i = 0; i < 4; i++)
        #pragma unroll
        for (int j = 0; j < 4; j++)
            #pragma unroll
            for (int q = 0; q < 4; q++) acc[i][j][q] = 0.0f;

    const int niter = Kd / 16;
    // prefetch stage 0
    #pragma unroll
    for (int i = 0; i < 2; i++) {
        cp16(daA[i], agp[i] + cc4[i], av[i]);
        cp16(daB[i], bgp[i] + cc4[i], true);
    }
    CP_COMMIT();

    for (int it = 0; it < niter; ++it) {
        CP_WAIT0();
        __syncthreads();
        if (it + 1 < niter) {
            int k0 = (it + 1) * 16;
            uint32_t off = ((it + 1) & 1) * STG_B;
            #pragma unroll
            for (int i = 0; i < 2; i++) {
                cp16(daA[i] + off, agp[i] + k0 + cc4[i], av[i]);
                cp16(daB[i] + off, bgp[i] + k0 + cc4[i], true);
            }
            CP_COMMIT();
        }
        const float* as = &As[it & 1][0];
        const float* bs = &Bs[it & 1][0];
        #pragma unroll
        for (int ks = 0; ks < 2; ks++) {
            int kb = ks * 8;
            float af[4][4];
            #pragma unroll
            for (int mt = 0; mt < 4; mt++) {
                int rb = wm * 64 + mt * 16;
                af[mt][0] = as[(rb + g)     * GSTRIDE + kb + tg];
                af[mt][1] = as[(rb + g + 8) * GSTRIDE + kb + tg];
                af[mt][2] = as[(rb + g)     * GSTRIDE + kb + tg + 4];
                af[mt][3] = as[(rb + g + 8) * GSTRIDE + kb + tg + 4];
            }
            float bf[4][2];
            #pragma unroll
            for (int nt = 0; nt < 4; nt++) {
                int nb = wn * 32 + nt * 8;
                bf[nt][0] = bs[(nb + g) * GSTRIDE + kb + tg];
                bf[nt][1] = bs[(nb + g) * GSTRIDE + kb + tg + 4];
            }
            #pragma unroll
            for (int mt = 0; mt < 4; mt++)
                #pragma unroll
                for (int nt = 0; nt < 4; nt++)
                    mma_tf32(acc[mt][nt][0], acc[mt][nt][1],
                             acc[mt][nt][2], acc[mt][nt][3],
                             af[mt][0], af[mt][1], af[mt][2], af[mt][3],
                             bf[nt][0], bf[nt][1]);
        }
    }

    #pragma unroll
    for (int mt = 0; mt < 4; mt++) {
        int r0 = bm + wm * 64 + mt * 16 + g;
        int r1 = r0 + 8;
        #pragma unroll
        for (int nt = 0; nt < 4; nt++) {
            int c = bn + wn * 32 + nt * 8 + 2 * tg;
            float bz0 = bias ? bias[c] : 0.f;
            float bz1 = bias ? bias[c + 1] : 0.f;
            if (r0 < M)
                *(float2*)(C + (long)r0 * ldc + c) =
                    make_float2(acc[mt][nt][0] + bz0, acc[mt][nt][1] + bz1);
            if (r1 < M)
                *(float2*)(C + (long)r1 * ldc + c) =
                    make_float2(acc[mt][nt][2] + bz0, acc[mt][nt][3] + bz1);
        }
    }
}

// ---------------- TF32 flash attention, cp.async double-buffered K/V ---------
// Block = 128 q-rows of one (b,h); 8 warps x 16 rows; 64-key tiles.
#define KS_STRIDE 132
#define VS_STRIDE 136
#define PS_STRIDE 68
#define KT_FLOATS (64 * KS_STRIDE)
#define VT_FLOATS (64 * VS_STRIDE)
#define FLASH_SMEM ((2*KT_FLOATS + 2*VT_FLOATS + 128*PS_STRIDE) * 4)

__global__ __launch_bounds__(256, 1)
void flash_tf32_kernel(float* __restrict__ qo,
                       const float* __restrict__ kbuf,
                       const float* __restrict__ vbuf) {
    const int qt = blockIdx.x, h = blockIdx.y, b = blockIdx.z;
    const int tid = threadIdx.x;
    const int w = tid >> 5, lane = tid & 31;
    const int g = lane >> 2, tg = lane & 3;
    const float scale = 0.08838834764831845f;   // 1/sqrt(128)

    extern __shared__ float sm[];
    float* KsBase = sm;                          // 2 x [64][132]
    float* VsBase = sm + 2 * KT_FLOATS;          // 2 x [64][136]
    float* Ps     = sm + 2 * KT_FLOATS + 2 * VT_FLOATS;  // [128][68]
    uint32_t ksB = smem_u32(KsBase), vsB = smem_u32(VsBase);

    const int qrow0 = qt * 128;
    float* qbase       = qo   + (long)b * KSEL_ * D_ + (long)h * HD_;
    const float* kbase = kbuf + (long)b * S2_ * D_ + (long)h * HD_;
    const float* vbase = vbuf + (long)b * S2_ * D_ + (long)h * HD_;

    const int r0g = qrow0 + w * 16 + g;
    const int r1g = r0g + 8;
    const bool v0 = r0g < KSEL_, v1 = r1g < KSEL_;
    float qf[16][4];
    {
        const float* q0 = qbase + (long)r0g * D_;
        const float* q1 = qbase + (long)r1g * D_;
        #pragma unroll
        for (int ks = 0; ks < 16; ks++) {
            int c0 = ks * 8 + tg, c1 = c0 + 4;
            qf[ks][0] = v0 ? q0[c0] * scale : 0.f;
            qf[ks][1] = v1 ? q1[c0] * scale : 0.f;
            qf[ks][2] = v0 ? q0[c1] * scale : 0.f;
            qf[ks][3] = v1 ? q1[c1] * scale : 0.f;
        }
    }

    float oacc[16][4];
    #pragma unroll
    for (int nt = 0; nt < 16; nt++)
        #pragma unroll
        for (int q = 0; q < 4; q++) oacc[nt][q] = 0.0f;
    float m0 = -1e30f, m1 = -1e30f, l0 = 0.f, l1 = 0.f;

    auto load_tile = [&](int t, int buf) {
        #pragma unroll
        for (int i = 0; i < 8; i++) {
            int idx = tid + i * 256;
            int r = idx >> 5, c4 = (idx & 31) << 2;
            long go = (long)(t * 64 + r) * D_ + c4;
            cp16(ksB + (buf * KT_FLOATS + r * KS_STRIDE + c4) * 4, kbase + go, true);
            cp16(vsB + (buf * VT_FLOATS + r * VS_STRIDE + c4) * 4, vbase + go, true);
        }
        CP_COMMIT();
    };

    load_tile(0, 0);
    const int NT = S2_ / 64;
    for (int t = 0; t < NT; ++t) {
        CP_WAIT0();
        __syncthreads();
        if (t + 1 < NT) load_tile(t + 1, (t + 1) & 1);
        const float* Ks = KsBase + (t & 1) * KT_FLOATS;
        const float* Vs = VsBase + (t & 1) * VT_FLOATS;

        // ---- S = Q K^T ----
        float sa[8][4];
        #pragma unroll
        for (int j = 0; j < 8; j++)
            #pragma unroll
            for (int q = 0; q < 4; q++) sa[j][q] = 0.0f;
        #pragma unroll
        for (int ks = 0; ks < 16; ks++) {
            int kb = ks * 8;
            #pragma unroll
            for (int j = 0; j < 8; j++) {
                float b0 = Ks[(j * 8 + g) * KS_STRIDE + kb + tg];
                float b1 = Ks[(j * 8 + g) * KS_STRIDE + kb + tg + 4];
                mma_tf32(sa[j][0], sa[j][1], sa[j][2], sa[j][3],
                         qf[ks][0], qf[ks][1], qf[ks][2], qf[ks][3], b0, b1);
            }
        }

        // ---- online softmax ----
        float rm0 = -1e30f, rm1 = -1e30f;
        #pragma unroll
        for (int j = 0; j < 8; j++) {
            rm0 = fmaxf(rm0, fmaxf(sa[j][0], sa[j][1]));
            rm1 = fmaxf(rm1, fmaxf(sa[j][2], sa[j][3]));
        }
        rm0 = fmaxf(rm0, __shfl_xor_sync(0xffffffffu, rm0, 1));
        rm0 = fmaxf(rm0, __shfl_xor_sync(0xffffffffu, rm0, 2));
        rm1 = fmaxf(rm1, __shfl_xor_sync(0xffffffffu, rm1, 1));
        rm1 = fmaxf(rm1, __shfl_xor_sync(0xffffffffu, rm1, 2));
        float mn0 = fmaxf(m0, rm0), mn1 = fmaxf(m1, rm1);
        float cr0 = __expf(m0 - mn0), cr1 = __expf(m1 - mn1);
        float ps0 = 0.f, ps1 = 0.f;
        #pragma unroll
        for (int j = 0; j < 8; j++) {
            sa[j][0] = __expf(sa[j][0] - mn0);
            sa[j][1] = __expf(sa[j][1] - mn0);
            sa[j][2] = __expf(sa[j][2] - mn1);
            sa[j][3] = __expf(sa[j][3] - mn1);
            ps0 += sa[j][0] + sa[j][1];
            ps1 += sa[j][2] + sa[j][3];
        }
        ps0 += __shfl_xor_sync(0xffffffffu, ps0, 1);
        ps0 += __shfl_xor_sync(0xffffffffu, ps0, 2);
        ps1 += __shfl_xor_sync(0xffffffffu, ps1, 1);
        ps1 += __shfl_xor_sync(0xffffffffu, ps1, 2);
        l0 = l0 * cr0 + ps0;  l1 = l1 * cr1 + ps1;
        m0 = mn0;             m1 = mn1;
        #pragma unroll
        for (int nt = 0; nt < 16; nt++) {
            oacc[nt][0] *= cr0; oacc[nt][1] *= cr0;
            oacc[nt][2] *= cr1; oacc[nt][3] *= cr1;
        }

        // stage P
        int pr0 = (w * 16 + g) * PS_STRIDE;
        int pr1 = (w * 16 + g + 8) * PS_STRIDE;
        #pragma unroll
        for (int j = 0; j < 8; j++) {
            int c = j * 8 + 2 * tg;
            Ps[pr0 + c]     = sa[j][0];
            Ps[pr0 + c + 1] = sa[j][1];
            Ps[pr1 + c]     = sa[j][2];
            Ps[pr1 + c + 1] = sa[j][3];
        }
        __syncthreads();

        // ---- O += P V ----
        #pragma unroll
        for (int ks = 0; ks < 8; ks++) {
            int kb = ks * 8;
            float a0 = Ps[pr0 + kb + tg];
            float a1 = Ps[pr1 + kb + tg];
            float a2 = Ps[pr0 + kb + tg + 4];
            float a3 = Ps[pr1 + kb + tg + 4];
            #pragma unroll
            for (int nt = 0; nt < 16; nt++) {
                float b0 = Vs[(kb + tg)     * VS_STRIDE + nt * 8 + g];
                float b1 = Vs[(kb + tg + 4) * VS_STRIDE + nt * 8 + g];
                mma_tf32(oacc[nt][0], oacc[nt][1], oacc[nt][2], oacc[nt][3],
                         a0, a1, a2, a3, b0, b1);
            }
        }
    }

    float i0 = 1.0f / l0, i1 = 1.0f / l1;
    #pragma unroll
    for (int nt = 0; nt < 16; nt++) {
        int c = nt * 8 + 2 * tg;
        if (v0) *(float2*)(qbase + (long)r0g * D_ + c) =
            make_float2(oacc[nt][0] * i0, oacc[nt][1] * i0);
        if (v1) *(float2*)(qbase + (long)r1g * D_ + c) =
            make_float2(oacc[nt][2] * i1, oacc[nt][3] * i1);
    }
}

// ---------------- final fuse -------------------------------------------------
__global__ void final_kernel(const float* __restrict__ base,
                             const float* __restrict__ attn,
                             const float* __restrict__ cth,
                             float* __restrict__ out) {
    int row = blockIdx.x;
    int tid = threadIdx.x;
    bool ok = (d_confsum * (1.0f / (float)(B_ * S2_)) > cth[0]);
    float g  = 1.0f / (1.0f + expf(-d_gatel[row]));
    float hg = 0.5f * g;
    int ro   = d_rowof[row];
    const float4* bp = (const float4*)(base + (long)row * D_);
    const float4* ap = (ro >= 0) ? (const float4*)(attn + (long)ro * D_) : bp;
    float4* op = (float4*)(out + (long)row * D_);
    float4 x = bp[tid], a = ap[tid], y;
    y.x = ok ? x.x + hg * a.x : x.x;
    y.y = ok ? x.y + hg * a.y : x.y;
    y.z = ok ? x.z + hg * a.z : x.z;
    y.w = ok ? x.w + hg * a.w : x.w;
    op[tid] = y;
}

// ---------------- host -------------------------------------------------------
static void run_gemm(bool gather,
                     const float* A, const float* Bm, const float* bias, float* C,
                     const int* grows, int M, int N, int Kd,
                     int lda, int ldb, int ldc) {
    dim3 grid(N / 128, (M + 127) / 128, 1);
    if (gather)
        tf32_gemm_kernel<true><<<grid, 256>>>(A, Bm, bias, C, grows,
                                              M, N, Kd, lda, ldb, ldc);
    else
        tf32_gemm_kernel<false><<<grid, 256>>>(A, Bm, bias, C, grows,
                                               M, N, Kd, lda, ldb, ldc);
}

extern "C" void kernel_launch(void* const* d_in, const int* in_sizes, int n_in,
                              void* d_out, int out_size) {
    const float* base     = (const float*)d_in[0];
    const float* scaffold = (const float*)d_in[1];
    const float* spw      = (const float*)d_in[2];
    const float* spb      = (const float*)d_in[3];
    const float* tkw      = (const float*)d_in[4];
    const float* tkb      = (const float*)d_in[5];
    const float* ipw      = (const float*)d_in[6];
    const float* ipb      = (const float*)d_in[7];
    const float* opw      = (const float*)d_in[8];
    const float* opb      = (const float*)d_in[9];
    const float* gw       = (const float*)d_in[10];
    const float* gb       = (const float*)d_in[11];
    const float* cth      = (const float*)d_in[12];
    float* out            = (float*)d_out;

    float* p_ws; float* p_scores; float* p_gatel; int* p_grows;
    cudaGetSymbolAddress((void**)&p_ws,     d_ws);
    cudaGetSymbolAddress((void**)&p_scores, d_scores);
    cudaGetSymbolAddress((void**)&p_gatel,  d_gatel);
    cudaGetSymbolAddress((void**)&p_grows,  d_grows);

    float* p_k    = p_ws + WS_K;
    float* p_v    = p_ws + WS_V;
    float* p_attn = p_ws + WS_ATTN;
    float* p_scaf = out;               // staged in d_out; dead before q written
    float* p_qo   = out;               // q, then o in-place; dead before final

    cudaFuncSetAttribute(flash_tf32_kernel,
                         cudaFuncAttributeMaxDynamicSharedMemorySize, FLASH_SMEM);

    init_kernel<<<64, 256>>>();
    rowdot2_kernel<<<(B_ * S_ * 32 + 255) / 256, 256>>>(
        base, tkw, tkb, gw, gb, p_scores, p_gatel, B_ * S_);
    {
        dim3 sg(S_ / 256, B_);
        select_kernel<<<sg, 256>>>();
    }

    // scaf = scaffold @ spw^T + spb -> d_out
    run_gemm(false, scaffold, spw, spb, p_scaf, nullptr,
             B_ * S2_, D_, SCAFD_, SCAFD_, SCAFD_, D_);
    norm_kernel<<<(B_ * S2_ * 32 + 255) / 256, 256>>>(p_scaf);

    // k, v -> d_ws
    run_gemm(false, p_scaf, ipw + (long)D_ * D_, ipb + D_, p_k, nullptr,
             B_ * S2_, D_, D_, D_, D_, D_);
    run_gemm(false, p_scaf, ipw + 2L * D_ * D_, ipb + 2 * D_, p_v, nullptr,
             B_ * S2_, D_, D_, D_, D_, D_);

    // q = gather(base) @ wq^T + bq -> d_out (scaf dead)
    run_gemm(true, base, ipw, ipb, p_qo, p_grows,
             BKROWS_, D_, D_, D_, D_, D_);

    // flash attention; o overwrites q in-place
    {
        dim3 grid((KSEL_ + 127) / 128, H_, B_);
        flash_tf32_kernel<<<grid, 256, FLASH_SMEM>>>(p_qo, p_k, p_v);
    }

    // attn = o @ opw^T + opb -> d_ws (k/v dead)
    run_gemm(false, p_qo, opw, opb, p_attn, nullptr,
             BKROWS_, D_, D_, D_, D_, D_);

    final_kernel<<<B_ * S_, 256>>>(base, p_attn, cth, out);
}

// round 14
// speedup vs baseline: 4.5767x; 1.0335x over previous
#include <cuda_runtime.h>
#include <math.h>
#include <stdint.h>

#define B_      4
#define S_      4096
#define S2_     2048
#define D_      1024
#define SCAFD_  768
#define H_      8
#define HD_     128
#define KSEL_   2549
#define BKROWS_ (B_*KSEL_)           // 10196

// ---------------- scratch ----------------------------------------------------
#define WS_K    0L
#define WS_V    8388608L
#define WS_ATTN 0L
__device__ float d_ws[16777216];     // 67.1 MB
__device__ float d_scores[B_*S_];
__device__ float d_gatel [B_*S_];
__device__ int   d_grows [BKROWS_];
__device__ int   d_rowof [B_*S_];
__device__ int   d_cnt   [B_];
__device__ float d_confsum;

// ---------------- helpers ----------------------------------------------------
__device__ __forceinline__ uint32_t smem_u32(const void* p) {
    return (uint32_t)__cvta_generic_to_shared(p);
}
__device__ __forceinline__ void cp16(uint32_t s, const void* g, bool v) {
    asm volatile("cp.async.cg.shared.global [%0], [%1], 16, %2;"
                 :: "r"(s), "l"(g), "r"(v ? 16 : 0));
}
#define CP_COMMIT() asm volatile("cp.async.commit_group;")
#define CP_WAIT0()  asm volatile("cp.async.wait_group 0;")

__device__ __forceinline__ void ldsm4(uint32_t& r0, uint32_t& r1,
                                      uint32_t& r2, uint32_t& r3, uint32_t a) {
    asm volatile("ldmatrix.sync.aligned.m8n8.x4.shared.b16 {%0,%1,%2,%3},[%4];"
                 : "=r"(r0), "=r"(r1), "=r"(r2), "=r"(r3) : "r"(a));
}
// tf32 mma, uint32 operand regs
__device__ __forceinline__ void mma_t32u(float& d0, float& d1, float& d2, float& d3,
                                         uint32_t a0, uint32_t a1, uint32_t a2, uint32_t a3,
                                         uint32_t b0, uint32_t b1) {
    asm volatile(
        "mma.sync.aligned.m16n8k8.row.col.f32.tf32.tf32.f32 "
        "{%0,%1,%2,%3}, {%4,%5,%6,%7}, {%8,%9}, {%0,%1,%2,%3};"
        : "+f"(d0), "+f"(d1), "+f"(d2), "+f"(d3)
        : "r"(a0), "r"(a1), "r"(a2), "r"(a3), "r"(b0), "r"(b1));
}
__device__ __forceinline__ void mma_tf32(float& d0, float& d1, float& d2, float& d3,
                                         float a0, float a1, float a2, float a3,
                                         float b0, float b1) {
    mma_t32u(d0, d1, d2, d3,
             __float_as_uint(a0), __float_as_uint(a1),
             __float_as_uint(a2), __float_as_uint(a3),
             __float_as_uint(b0), __float_as_uint(b1));
}

// ---------------- init -------------------------------------------------------
__global__ void init_kernel() {
    int i = blockIdx.x * blockDim.x + threadIdx.x;
    if (i < B_*S_) d_rowof[i] = -1;
    if (i < B_)    d_cnt[i]   = 0;
    if (i == 0)    d_confsum  = 0.0f;
}

// ---------------- exact fp32 dual row-dot ------------------------------------
__global__ void rowdot2_kernel(const float* __restrict__ X,
                               const float* __restrict__ w1, const float* __restrict__ b1,
                               const float* __restrict__ w2, const float* __restrict__ b2,
                               float* __restrict__ o1, float* __restrict__ o2, int nrows) {
    int warp = (blockIdx.x * blockDim.x + threadIdx.x) >> 5;
    int lane = threadIdx.x & 31;
    if (warp >= nrows) return;
    const float4* x4 = (const float4*)(X + (long)warp * D_);
    const float4* u4 = (const float4*)w1;
    const float4* v4 = (const float4*)w2;
    float s1 = 0.f, s2 = 0.f;
    for (int i = lane; i < D_/4; i += 32) {
        float4 a = x4[i], u = u4[i], v = v4[i];
        s1 += a.x*u.x + a.y*u.y + a.z*u.z + a.w*u.w;
        s2 += a.x*v.x + a.y*v.y + a.z*v.z + a.w*v.w;
    }
    #pragma unroll
    for (int off = 16; off; off >>= 1) {
        s1 += __shfl_xor_sync(0xffffffffu, s1, off);
        s2 += __shfl_xor_sync(0xffffffffu, s2, off);
    }
    if (lane == 0) { o1[warp] = s1 + b1[0]; o2[warp] = s2 + b2[0]; }
}

// ---------------- mean row-norm of scaf --------------------------------------
__global__ void norm_kernel(const float* __restrict__ scaf) {
    int warp = (blockIdx.x * blockDim.x + threadIdx.x) >> 5;
    int lane = threadIdx.x & 31;
    if (warp >= B_*S2_) return;
    const float4* x4 = (const float4*)(scaf + (long)warp * D_);
    float s = 0.f;
    for (int i = lane; i < D_/4; i += 32) {
        float4 a = x4[i];
        s += a.x*a.x + a.y*a.y + a.z*a.z + a.w*a.w;
    }
    #pragma unroll
    for (int off = 16; off; off >>= 1) s += __shfl_xor_sync(0xffffffffu, s, off);
    if (lane == 0) atomicAdd(&d_confsum, sqrtf(s));
}

// ---------------- exact top-K via rank counting ------------------------------
__global__ void select_kernel() {
    __shared__ float sh[S_];
    int b = blockIdx.y;
    const float* sc = d_scores + b * S_;
    for (int i = threadIdx.x; i < S_; i += 256) sh[i] = sc[i];
    __syncthreads();
    int cand = blockIdx.x * 256 + threadIdx.x;
    float myv = sh[cand];
    int cnt = 0;
    for (int j = 0; j < S_; j += 4) {
        float4 v = *(const float4*)&sh[j];
        cnt += (v.x > myv) || (v.x == myv && (j + 0) < cand);
        cnt += (v.y > myv) || (v.y == myv && (j + 1) < cand);
        cnt += (v.z > myv) || (v.z == myv && (j + 2) < cand);
        cnt += (v.w > myv) || (v.w == myv && (j + 3) < cand);
    }
    if (cnt < KSEL_) {
        int pos = atomicAdd(&d_cnt[b], 1);
        d_grows[b * KSEL_ + pos] = b * S_ + cand;
        d_rowof[b * S_ + cand]   = b * KSEL_ + pos;
    }
}

// ---------------- TF32 GEMM: cp.async 2-stage + ldmatrix fragments -----------
// 128x128 tile, BK=16, 8 warps (2m x 4n), each 64x32 via m16n8k8.
#define GSTRIDE 20
#define STG_B   (128 * GSTRIDE * 4)

template <bool GATHER>
__global__ __launch_bounds__(256)
void tf32_gemm_kernel(const float* __restrict__ A, const float* __restrict__ Bm,
                      const float* __restrict__ bias, float* __restrict__ C,
                      const int* __restrict__ grows,
                      int M, int N, int Kd, int lda, int ldb, int ldc) {
    __shared__ __align__(16) float As[2][128 * GSTRIDE];
    __shared__ __align__(16) float Bs[2][128 * GSTRIDE];

    const int tid  = threadIdx.x;
    const int w    = tid >> 5, lane = tid & 31;
    const int g    = lane >> 2, tg = lane & 3;
    const int l8   = lane & 7,  sub = lane >> 3;
    const int wm   = w & 1, wn = w >> 1;
    const int bm   = blockIdx.y * 128;
    const int bn   = blockIdx.x * 128;

    // copy map: 2 chunks per thread per matrix
    int crow[2], cc4[2]; bool av[2];
    const float* agp[2]; const float* bgp[2];
    uint32_t daA[2], daB[2];
    uint32_t sa0 = smem_u32(&As[0][0]), sb0 = smem_u32(&Bs[0][0]);
    #pragma unroll
    for (int i = 0; i < 2; i++) {
        int idx = tid + i * 256;
        crow[i] = idx >> 2; cc4[i] = (idx & 3) << 2;
        av[i] = (bm + crow[i]) < M;
        long arow = av[i] ? (GATHER ? (long)grows[bm + crow[i]]
                                    : (long)(bm + crow[i])) : 0;
        agp[i] = A + arow * (long)lda;
        bgp[i] = Bm + (long)(bn + crow[i]) * ldb;
        daA[i] = sa0 + (crow[i] * GSTRIDE + cc4[i]) * 4;
        daB[i] = sb0 + (crow[i] * GSTRIDE + cc4[i]) * 4;
    }

    // ldmatrix address offsets (row/col pattern shared by A and B tiles)
    const int lrow = (sub >> 1) * 8 + l8;      // +0..15
    const int lcol = (sub & 1) * 4;            // 0 or 4

    float acc[4][4][4];
    #pragma unroll
    for (int i = 0; i < 4; i++)
        #pragma unroll
        for (int j = 0; j < 4; j++)
            #pragma unroll
            for (int q = 0; q < 4; q++) acc[i][j][q] = 0.0f;

    const int niter = Kd / 16;
    #pragma unroll
    for (int i = 0; i < 2; i++) {
        cp16(daA[i], agp[i] + cc4[i], av[i]);
        cp16(daB[i], bgp[i] + cc4[i], true);
    }
    CP_COMMIT();

    for (int it = 0; it < niter; ++it) {
        CP_WAIT0();
        __syncthreads();
        if (it + 1 < niter) {
            int k0 = (it + 1) * 16;
            uint32_t off = ((it + 1) & 1) * STG_B;
            #pragma unroll
            for (int i = 0; i < 2; i++) {
                cp16(daA[i] + off, agp[i] + k0 + cc4[i], av[i]);
                cp16(daB[i] + off, bgp[i] + k0 + cc4[i], true);
            }
            CP_COMMIT();
        }
        uint32_t ab = sa0 + (it & 1) * STG_B;
        uint32_t bb = sb0 + (it & 1) * STG_B;
        #pragma unroll
        for (int ks = 0; ks < 2; ks++) {
            int kb = ks * 8;
            uint32_t af[4][4];
            #pragma unroll
            for (int mt = 0; mt < 4; mt++) {
                int rb = wm * 64 + mt * 16;
                uint32_t r0, r1, r2, r3;
                ldsm4(r0, r1, r2, r3,
                      ab + ((rb + lrow) * GSTRIDE + kb + lcol) * 4);
                af[mt][0] = r0; af[mt][1] = r2;   // (a0,a1,a2,a3)=(r0,r2,r1,r3)
                af[mt][2] = r1; af[mt][3] = r3;
            }
            uint32_t bf[4][2];
            #pragma unroll
            for (int p = 0; p < 2; p++) {
                int nb = wn * 32 + p * 16;
                uint32_t r0, r1, r2, r3;
                ldsm4(r0, r1, r2, r3,
                      bb + ((nb + lrow) * GSTRIDE + kb + lcol) * 4);
                bf[2*p][0] = r0;   bf[2*p][1] = r1;
                bf[2*p+1][0] = r2; bf[2*p+1][1] = r3;
            }
            #pragma unroll
            for (int mt = 0; mt < 4; mt++)
                #pragma unroll
                for (int nt = 0; nt < 4; nt++)
                    mma_t32u(acc[mt][nt][0], acc[mt][nt][1],
                             acc[mt][nt][2], acc[mt][nt][3],
                             af[mt][0], af[mt][1], af[mt][2], af[mt][3],
                             bf[nt][0], bf[nt][1]);
        }
    }

    #pragma unroll
    for (int mt = 0; mt < 4; mt++) {
        int r0 = bm + wm * 64 + mt * 16 + g;
        int r1 = r0 + 8;
        #pragma unroll
        for (int nt = 0; nt < 4; nt++) {
            int c = bn + wn * 32 + nt * 8 + 2 * tg;
            float bz0 = bias ? bias[c] : 0.f;
            float bz1 = bias ? bias[c + 1] : 0.f;
            if (r0 < M)
                *(float2*)(C + (long)r0 * ldc + c) =
                    make_float2(acc[mt][nt][0] + bz0, acc[mt][nt][1] + bz1);
            if (r1 < M)
                *(float2*)(C + (long)r1 * ldc + c) =
                    make_float2(acc[mt][nt][2] + bz0, acc[mt][nt][3] + bz1);
        }
    }
}

// ---------------- TF32 flash attention (ldmatrix K/P, cp.async K/V) ----------
#define KS_STRIDE 132
#define VS_STRIDE 136
#define PS_STRIDE 68
#define KT_FLOATS (64 * KS_STRIDE)
#define VT_FLOATS (64 * VS_STRIDE)
#define FLASH_SMEM ((2*KT_FLOATS + 2*VT_FLOATS + 128*PS_STRIDE) * 4)

__global__ __launch_bounds__(256, 1)
void flash_tf32_kernel(float* __restrict__ qo,
                       const float* __restrict__ kbuf,
                       const float* __restrict__ vbuf) {
    const int qt = blockIdx.x, h = blockIdx.y, b = blockIdx.z;
    const int tid = threadIdx.x;
    const int w = tid >> 5, lane = tid & 31;
    const int g = lane >> 2, tg = lane & 3;
    const int l8 = lane & 7, sub = lane >> 3;
    const float scale = 0.08838834764831845f;   // 1/sqrt(128)

    extern __shared__ float sm[];
    float* KsBase = sm;                          // 2 x [64][132]
    float* VsBase = sm + 2 * KT_FLOATS;          // 2 x [64][136]
    float* Ps     = sm + 2 * KT_FLOATS + 2 * VT_FLOATS;  // [128][68]
    uint32_t ksB = smem_u32(KsBase), vsB = smem_u32(VsBase);
    uint32_t psB = smem_u32(Ps);

    const int lrow = (sub >> 1) * 8 + l8;
    const int lcol = (sub & 1) * 4;

    const int qrow0 = qt * 128;
    float* qbase       = qo   + (long)b * KSEL_ * D_ + (long)h * HD_;
    const float* kbase = kbuf + (long)b * S2_ * D_ + (long)h * HD_;
    const float* vbase = vbuf + (long)b * S2_ * D_ + (long)h * HD_;

    const int r0g = qrow0 + w * 16 + g;
    const int r1g = r0g + 8;
    const bool v0 = r0g < KSEL_, v1 = r1g < KSEL_;
    float qf[16][4];
    {
        const float* q0 = qbase + (long)r0g * D_;
        const float* q1 = qbase + (long)r1g * D_;
        #pragma unroll
        for (int ks = 0; ks < 16; ks++) {
            int c0 = ks * 8 + tg, c1 = c0 + 4;
            qf[ks][0] = v0 ? q0[c0] * scale : 0.f;
            qf[ks][1] = v1 ? q1[c0] * scale : 0.f;
            qf[ks][2] = v0 ? q0[c1] * scale : 0.f;
            qf[ks][3] = v1 ? q1[c1] * scale : 0.f;
        }
    }

    float oacc[16][4];
    #pragma unroll
    for (int nt = 0; nt < 16; nt++)
        #pragma unroll
        for (int q = 0; q < 4; q++) oacc[nt][q] = 0.0f;
    float m0 = -1e30f, m1 = -1e30f, l0 = 0.f, l1 = 0.f;

    auto load_tile = [&](int t, int buf) {
        #pragma unroll
        for (int i = 0; i < 8; i++) {
            int idx = tid + i * 256;
            int r = idx >> 5, c4 = (idx & 31) << 2;
            long go = (long)(t * 64 + r) * D_ + c4;
            cp16(ksB + (buf * KT_FLOATS + r * KS_STRIDE + c4) * 4, kbase + go, true);
            cp16(vsB + (buf * VT_FLOATS + r * VS_STRIDE + c4) * 4, vbase + go, true);
        }
        CP_COMMIT();
    };

    load_tile(0, 0);
    const int NT = S2_ / 64;
    for (int t = 0; t < NT; ++t) {
        CP_WAIT0();
        __syncthreads();
        if (t + 1 < NT) load_tile(t + 1, (t + 1) & 1);
        uint32_t kTile = ksB + (t & 1) * KT_FLOATS * 4;
        const float* Vs = VsBase + (t & 1) * VT_FLOATS;

        // ---- S = Q K^T (K b-frags via ldmatrix; 4 per ks cover n64) ----
        float sa[8][4];
        #pragma unroll
        for (int j = 0; j < 8; j++)
            #pragma unroll
            for (int q = 0; q < 4; q++) sa[j][q] = 0.0f;
        #pragma unroll
        for (int ks = 0; ks < 16; ks++) {
            int kb = ks * 8;
            #pragma unroll
            for (int j16 = 0; j16 < 4; j16++) {
                uint32_t r0, r1, r2, r3;
                ldsm4(r0, r1, r2, r3,
                      kTile + ((j16 * 16 + lrow) * KS_STRIDE + kb + lcol) * 4);
                int j = j16 * 2;
                mma_tf32(sa[j][0], sa[j][1], sa[j][2], sa[j][3],
                         qf[ks][0], qf[ks][1], qf[ks][2], qf[ks][3],
                         __uint_as_float(r0), __uint_as_float(r1));
                mma_tf32(sa[j+1][0], sa[j+1][1], sa[j+1][2], sa[j+1][3],
                         qf[ks][0], qf[ks][1], qf[ks][2], qf[ks][3],
                         __uint_as_float(r2), __uint_as_float(r3));
            }
        }

        // ---- online softmax ----
        float rm0 = -1e30f, rm1 = -1e30f;
        #pragma unroll
        for (int j = 0; j < 8; j++) {
            rm0 = fmaxf(rm0, fmaxf(sa[j][0], sa[j][1]));
            rm1 = fmaxf(rm1, fmaxf(sa[j][2], sa[j][3]));
        }
        rm0 = fmaxf(rm0, __shfl_xor_sync(0xffffffffu, rm0, 1));
        rm0 = fmaxf(rm0, __shfl_xor_sync(0xffffffffu, rm0, 2));
        rm1 = fmaxf(rm1, __shfl_xor_sync(0xffffffffu, rm1, 1));
        rm1 = fmaxf(rm1, __shfl_xor_sync(0xffffffffu, rm1, 2));
        float mn0 = fmaxf(m0, rm0), mn1 = fmaxf(m1, rm1);
        float cr0 = __expf(m0 - mn0), cr1 = __expf(m1 - mn1);
        float ps0 = 0.f, ps1 = 0.f;
        #pragma unroll
        for (int j = 0; j < 8; j++) {
            sa[j][0] = __expf(sa[j][0] - mn0);
            sa[j][1] = __expf(sa[j][1] - mn0);
            sa[j][2] = __expf(sa[j][2] - mn1);
            sa[j][3] = __expf(sa[j][3] - mn1);
            ps0 += sa[j][0] + sa[j][1];
            ps1 += sa[j][2] + sa[j][3];
        }
        ps0 += __shfl_xor_sync(0xffffffffu, ps0, 1);
        ps0 += __shfl_xor_sync(0xffffffffu, ps0, 2);
        ps1 += __shfl_xor_sync(0xffffffffu, ps1, 1);
        ps1 += __shfl_xor_sync(0xffffffffu, ps1, 2);
        l0 = l0 * cr0 + ps0;  l1 = l1 * cr1 + ps1;
        m0 = mn0;             m1 = mn1;
        #pragma unroll
        for (int nt = 0; nt < 16; nt++) {
            oacc[nt][0] *= cr0; oacc[nt][1] *= cr0;
            oacc[nt][2] *= cr1; oacc[nt][3] *= cr1;
        }

        // stage P
        int pr0 = (w * 16 + g) * PS_STRIDE;
        int pr1 = (w * 16 + g + 8) * PS_STRIDE;
        #pragma unroll
        for (int j = 0; j < 8; j++) {
            int c = j * 8 + 2 * tg;
            Ps[pr0 + c]     = sa[j][0];
            Ps[pr0 + c + 1] = sa[j][1];
            Ps[pr1 + c]     = sa[j][2];
            Ps[pr1 + c + 1] = sa[j][3];
        }
        __syncthreads();

        // ---- O += P V (P a-frags via ldmatrix; V scalar, conflict-free) ----
        #pragma unroll
        for (int ks = 0; ks < 8; ks++) {
            int kb = ks * 8;
            uint32_t p0, p1, p2, p3;
            ldsm4(p0, p1, p2, p3,
                  psB + ((w * 16 + lrow) * PS_STRIDE + kb + lcol) * 4);
            // (a0,a1,a2,a3) = (p0,p2,p1,p3)
            #pragma unroll
            for (int nt = 0; nt < 16; nt++) {
                float b0 = Vs[(kb + tg)     * VS_STRIDE + nt * 8 + g];
                float b1 = Vs[(kb + tg + 4) * VS_STRIDE + nt * 8 + g];
                mma_t32u(oacc[nt][0], oacc[nt][1], oacc[nt][2], oacc[nt][3],
                         p0, p2, p1, p3,
                         __float_as_uint(b0), __float_as_uint(b1));
            }
        }
        __syncthreads();
    }

    float i0 = 1.0f / l0, i1 = 1.0f / l1;
    #pragma unroll
    for (int nt = 0; nt < 16; nt++) {
        int c = nt * 8 + 2 * tg;
        if (v0) *(float2*)(qbase + (long)r0g * D_ + c) =
            make_float2(oacc[nt][0] * i0, oacc[nt][1] * i0);
        if (v1) *(float2*)(qbase + (long)r1g * D_ + c) =
            make_float2(oacc[nt][2] * i1, oacc[nt][3] * i1);
    }
}

// ---------------- final fuse -------------------------------------------------
__global__ void final_kernel(const float* __restrict__ base,
                             const float* __restrict__ attn,
                             const float* __restrict__ cth,
                             float* __restrict__ out) {
    int row = blockIdx.x;
    int tid = threadIdx.x;
    bool ok = (d_confsum * (1.0f / (float)(B_ * S2_)) > cth[0]);
    float g  = 1.0f / (1.0f + expf(-d_gatel[row]));
    float hg = 0.5f * g;
    int ro   = d_rowof[row];
    const float4* bp = (const float4*)(base + (long)row * D_);
    const float4* ap = (ro >= 0) ? (const float4*)(attn + (long)ro * D_) : bp;
    float4* op = (float4*)(out + (long)row * D_);
    float4 x = bp[tid], a = ap[tid], y;
    y.x = ok ? x.x + hg * a.x : x.x;
    y.y = ok ? x.y + hg * a.y : x.y;
    y.z = ok ? x.z + hg * a.z : x.z;
    y.w = ok ? x.w + hg * a.w : x.w;
    op[tid] = y;
}

// ---------------- host -------------------------------------------------------
static void run_gemm(bool gather,
                     const float* A, const float* Bm, const float* bias, float* C,
                     const int* grows, int M, int N, int Kd,
                     int lda, int ldb, int ldc) {
    dim3 grid(N / 128, (M + 127) / 128, 1);
    if (gather)
        tf32_gemm_kernel<true><<<grid, 256>>>(A, Bm, bias, C, grows,
                                              M, N, Kd, lda, ldb, ldc);
    else
        tf32_gemm_kernel<false><<<grid, 256>>>(A, Bm, bias, C, grows,
                                               M, N, Kd, lda, ldb, ldc);
}

extern "C" void kernel_launch(void* const* d_in, const int* in_sizes, int n_in,
                              void* d_out, int out_size) {
    const float* base     = (const float*)d_in[0];
    const float* scaffold = (const float*)d_in[1];
    const float* spw      = (const float*)d_in[2];
    const float* spb      = (const float*)d_in[3];
    const float* tkw      = (const float*)d_in[4];
    const float* tkb      = (const float*)d_in[5];
    const float* ipw      = (const float*)d_in[6];
    const float* ipb      = (const float*)d_in[7];
    const float* opw      = (const float*)d_in[8];
    const float* opb      = (const float*)d_in[9];
    const float* gw       = (const float*)d_in[10];
    const float* gb       = (const float*)d_in[11];
    const float* cth      = (const float*)d_in[12];
    float* out            = (float*)d_out;

    float* p_ws; float* p_scores; float* p_gatel; int* p_grows;
    cudaGetSymbolAddress((void**)&p_ws,     d_ws);
    cudaGetSymbolAddress((void**)&p_scores, d_scores);
    cudaGetSymbolAddress((void**)&p_gatel,  d_gatel);
    cudaGetSymbolAddress((void**)&p_grows,  d_grows);

    float* p_k    = p_ws + WS_K;
    float* p_v    = p_ws + WS_V;
    float* p_attn = p_ws + WS_ATTN;
    float* p_scaf = out;               // staged in d_out; dead before q written
    float* p_qo   = out;               // q, then o in-place; dead before final

    cudaFuncSetAttribute(flash_tf32_kernel,
                         cudaFuncAttributeMaxDynamicSharedMemorySize, FLASH_SMEM);

    init_kernel<<<64, 256>>>();
    rowdot2_kernel<<<(B_ * S_ * 32 + 255) / 256, 256>>>(
        base, tkw, tkb, gw, gb, p_scores, p_gatel, B_ * S_);
    {
        dim3 sg(S_ / 256, B_);
        select_kernel<<<sg, 256>>>();
    }

    // scaf = scaffold @ spw^T + spb -> d_out
    run_gemm(false, scaffold, spw, spb, p_scaf, nullptr,
             B_ * S2_, D_, SCAFD_, SCAFD_, SCAFD_, D_);
    norm_kernel<<<(B_ * S2_ * 32 + 255) / 256, 256>>>(p_scaf);

    // k, v -> d_ws
    run_gemm(false, p_scaf, ipw + (long)D_ * D_, ipb + D_, p_k, nullptr,
             B_ * S2_, D_, D_, D_, D_, D_);
    run_gemm(false, p_scaf, ipw + 2L * D_ * D_, ipb + 2 * D_, p_v, nullptr,
             B_ * S2_, D_, D_, D_, D_, D_);

    // q = gather(base) @ wq^T + bq -> d_out (scaf dead)
    run_gemm(true, base, ipw, ipb, p_qo, p_grows,
             BKROWS_, D_, D_, D_, D_, D_);

    // flash attention; o overwrites q in-place
    {
        dim3 grid((KSEL_ + 127) / 128, H_, B_);
        flash_tf32_kernel<<<grid, 256, FLASH_SMEM>>>(p_qo, p_k, p_v);
    }

    // attn = o @ opw^T + opb -> d_ws (k/v dead)
    run_gemm(false, p_qo, opw, opb, p_attn, nullptr,
             BKROWS_, D_, D_, D_, D_, D_);

    final_kernel<<<B_ * S_, 256>>>(base, p_attn, cth, out);
}

// round 16
// speedup vs baseline: 7.6805x; 1.6782x over previous
#include <cuda_runtime.h>
#include <cuda_fp16.h>
#include <math.h>
#include <stdint.h>

#define B_      4
#define S_      4096
#define S2_     2048
#define D_      1024
#define SCAFD_  768
#define H_      8
#define HD_     128
#define KSEL_   2549
#define BKROWS_ (B_*KSEL_)           // 10196

typedef __half fp16;

// ---------------- scratch (offsets in floats; lifetimes disjoint) ------------
// d_ws: ATTN fp32 [0,10440704)         live: attn GEMM .. final
//       KH fp16   [0,4194304)          live: k GEMM .. flash (dead before ATTN)
//       VH fp16   [4194304,8388608)    live: v GEMM .. flash
//       SCAFH     [8388608,12582912)   live: scaf GEMM .. v GEMM
//       SPWH      [12582912,12976128)  393216 floats  (D*SCAFD halves)
//       IPWH      [12976128,14548992)  1572864 floats (3*D*D halves)
//       OPWH      [14548992,15073280)  524288 floats  (D*D halves)
#define WS_ATTN   0L
#define WS_KH     0L
#define WS_VH     4194304L
#define WS_SCAFH  8388608L
#define WS_SPWH   12582912L
#define WS_IPWH   12976128L
#define WS_OPWH   14548992L
__device__ float d_ws[16777216];     // 67.1 MB
__device__ float d_scores[B_*S_];
__device__ float d_gatel [B_*S_];
__device__ int   d_grows [BKROWS_];
__device__ int   d_rowof [B_*S_];
__device__ int   d_cnt   [B_];
__device__ float d_confsum;
// d_out scratch: BASEH fp16 [0,8388608) live cvt..q-GEMM; SCFH [8388608,11534336)
// live cvt..scaf-GEMM; QH (q then o) [11534336,16754688) live q-GEMM..attn-GEMM.
// final_kernel rewrites all of d_out last.
#define DO_BASEH 0L
#define DO_SCFH  8388608L
#define DO_QH    11534336L

// ---------------- helpers ----------------------------------------------------
__device__ __forceinline__ uint32_t smem_u32(const void* p) {
    return (uint32_t)__cvta_generic_to_shared(p);
}
__device__ __forceinline__ void cp16(uint32_t s, const void* g, bool v) {
    asm volatile("cp.async.cg.shared.global [%0], [%1], 16, %2;"
                 :: "r"(s), "l"(g), "r"(v ? 16 : 0));
}
#define CP_COMMIT() asm volatile("cp.async.commit_group;")
#define CP_WAIT0()  asm volatile("cp.async.wait_group 0;")
__device__ __forceinline__ void ldsm4(uint32_t& r0, uint32_t& r1,
                                      uint32_t& r2, uint32_t& r3, uint32_t a) {
    asm volatile("ldmatrix.sync.aligned.m8n8.x4.shared.b16 {%0,%1,%2,%3},[%4];"
                 : "=r"(r0), "=r"(r1), "=r"(r2), "=r"(r3) : "r"(a));
}
__device__ __forceinline__ void ldsm4t(uint32_t& r0, uint32_t& r1,
                                       uint32_t& r2, uint32_t& r3, uint32_t a) {
    asm volatile("ldmatrix.sync.aligned.m8n8.x4.trans.shared.b16 {%0,%1,%2,%3},[%4];"
                 : "=r"(r0), "=r"(r1), "=r"(r2), "=r"(r3) : "r"(a));
}
__device__ __forceinline__ void mma_h(float& d0, float& d1, float& d2, float& d3,
                                      uint32_t a0, uint32_t a1, uint32_t a2, uint32_t a3,
                                      uint32_t b0, uint32_t b1) {
    asm volatile(
        "mma.sync.aligned.m16n8k16.row.col.f32.f16.f16.f32 "
        "{%0,%1,%2,%3}, {%4,%5,%6,%7}, {%8,%9}, {%0,%1,%2,%3};"
        : "+f"(d0), "+f"(d1), "+f"(d2), "+f"(d3)
        : "r"(a0), "r"(a1), "r"(a2), "r"(a3), "r"(b0), "r"(b1));
}
__device__ __forceinline__ uint32_t packh(float lo, float hi) {
    __half2 h = __floats2half2_rn(lo, hi);
    return *(uint32_t*)&h;
}

// ---------------- fp32 -> fp16 -----------------------------------------------
__global__ void cvt_kernel(const float4* __restrict__ s, uint2* __restrict__ d, int n4) {
    int i = blockIdx.x * blockDim.x + threadIdx.x;
    if (i >= n4) return;
    float4 v = s[i];
    d[i] = make_uint2(packh(v.x, v.y), packh(v.z, v.w));
}

// ---------------- init -------------------------------------------------------
__global__ void init_kernel() {
    int i = blockIdx.x * blockDim.x + threadIdx.x;
    if (i < B_*S_) d_rowof[i] = -1;
    if (i < B_)    d_cnt[i]   = 0;
    if (i == 0)    d_confsum  = 0.0f;
}

// ---------------- exact fp32 dual row-dot ------------------------------------
__global__ void rowdot2_kernel(const float* __restrict__ X,
                               const float* __restrict__ w1, const float* __restrict__ b1,
                               const float* __restrict__ w2, const float* __restrict__ b2,
                               float* __restrict__ o1, float* __restrict__ o2, int nrows) {
    int warp = (blockIdx.x * blockDim.x + threadIdx.x) >> 5;
    int lane = threadIdx.x & 31;
    if (warp >= nrows) return;
    const float4* x4 = (const float4*)(X + (long)warp * D_);
    const float4* u4 = (const float4*)w1;
    const float4* v4 = (const float4*)w2;
    float s1 = 0.f, s2 = 0.f;
    for (int i = lane; i < D_/4; i += 32) {
        float4 a = x4[i], u = u4[i], v = v4[i];
        s1 += a.x*u.x + a.y*u.y + a.z*u.z + a.w*u.w;
        s2 += a.x*v.x + a.y*v.y + a.z*v.z + a.w*v.w;
    }
    #pragma unroll
    for (int off = 16; off; off >>= 1) {
        s1 += __shfl_xor_sync(0xffffffffu, s1, off);
        s2 += __shfl_xor_sync(0xffffffffu, s2, off);
    }
    if (lane == 0) { o1[warp] = s1 + b1[0]; o2[warp] = s2 + b2[0]; }
}

// ---------------- mean row-norm of scaf_h ------------------------------------
__global__ void norm_kernel(const fp16* __restrict__ scaf) {
    int warp = (blockIdx.x * blockDim.x + threadIdx.x) >> 5;
    int lane = threadIdx.x & 31;
    if (warp >= B_*S2_) return;
    const __half2* x = (const __half2*)(scaf + (long)warp * D_);
    float s = 0.f;
    for (int i = lane; i < D_/2; i += 32) {
        float2 f = __half22float2(x[i]);
        s += f.x*f.x + f.y*f.y;
    }
    #pragma unroll
    for (int off = 16; off; off >>= 1) s += __shfl_xor_sync(0xffffffffu, s, off);
    if (lane == 0) atomicAdd(&d_confsum, sqrtf(s));
}

// ---------------- exact top-K via rank counting ------------------------------
__global__ void select_kernel() {
    __shared__ float sh[S_];
    int b = blockIdx.y;
    const float* sc = d_scores + b * S_;
    for (int i = threadIdx.x; i < S_; i += 256) sh[i] = sc[i];
    __syncthreads();
    int cand = blockIdx.x * 256 + threadIdx.x;
    float myv = sh[cand];
    int cnt = 0;
    for (int j = 0; j < S_; j += 4) {
        float4 v = *(const float4*)&sh[j];
        cnt += (v.x > myv) || (v.x == myv && (j + 0) < cand);
        cnt += (v.y > myv) || (v.y == myv && (j + 1) < cand);
        cnt += (v.z > myv) || (v.z == myv && (j + 2) < cand);
        cnt += (v.w > myv) || (v.w == myv && (j + 3) < cand);
    }
    if (cnt < KSEL_) {
        int pos = atomicAdd(&d_cnt[b], 1);
        d_grows[b * KSEL_ + pos] = b * S_ + cand;
        d_rowof[b * S_ + cand]   = b * KSEL_ + pos;
    }
}

// ---------------- fp16 GEMM: C = A @ W^T + bias ------------------------------
// 128x128 tile, BK=32, 8 warps (2m x 4n), each 64x32. cp.async 2-stage.
#define GSTR 40
template <bool GATHER, bool OUTH>
__global__ __launch_bounds__(256)
void gemm_h_kernel(const fp16* __restrict__ A, const fp16* __restrict__ W,
                   const float* __restrict__ bias, void* __restrict__ Cv,
                   const int* __restrict__ grows,
                   int M, int N, int Kd, int lda, int ldb, int ldc) {
    __shared__ fp16 sA[2][128 * GSTR];
    __shared__ fp16 sB[2][128 * GSTR];
    const int tid = threadIdx.x;
    const int w = tid >> 5, lane = tid & 31;
    const int g = lane >> 2, tg = lane & 3;
    const int l8 = lane & 7, sub = lane >> 3;
    const int wm = w & 1, wn = w >> 1;
    const int bm = blockIdx.y * 128, bn = blockIdx.x * 128;

    const int crow = tid >> 1, cc = (tid & 1) * 16;
    bool av = (bm + crow) < M;
    long arow = av ? (GATHER ? (long)grows[bm + crow] : (long)(bm + crow)) : 0;
    const fp16* agp = A + arow * lda;
    const fp16* bgp = W + (long)(bn + crow) * ldb;
    uint32_t saB = smem_u32(&sA[0][0]), sbB = smem_u32(&sB[0][0]);
    const uint32_t stg = 128 * GSTR * 2;
    uint32_t da = saB + (crow * GSTR + cc) * 2;
    uint32_t db = sbB + (crow * GSTR + cc) * 2;

    float acc[4][4][4];
    #pragma unroll
    for (int i = 0; i < 4; i++)
        #pragma unroll
        for (int j = 0; j < 4; j++)
            #pragma unroll
            for (int q = 0; q < 4; q++) acc[i][j][q] = 0.f;

    const int niter = Kd / 32;
    cp16(da, agp + cc, av);      cp16(da + 16, agp + cc + 8, av);
    cp16(db, bgp + cc, true);    cp16(db + 16, bgp + cc + 8, true);
    CP_COMMIT();

    for (int it = 0; it < niter; ++it) {
        CP_WAIT0();
        __syncthreads();
        if (it + 1 < niter) {
            int k0 = (it + 1) * 32;
            uint32_t off = ((it + 1) & 1) * stg;
            cp16(da + off,      agp + k0 + cc,     av);
            cp16(da + off + 16, agp + k0 + cc + 8, av);
            cp16(db + off,      bgp + k0 + cc,     true);
            cp16(db + off + 16, bgp + k0 + cc + 8, true);
            CP_COMMIT();
        }
        uint32_t ab = saB + (it & 1) * stg, bb = sbB + (it & 1) * stg;
        #pragma unroll
        for (int ks = 0; ks < 2; ks++) {
            uint32_t aF[4][4], bF[4][2];
            #pragma unroll
            for (int mt = 0; mt < 4; mt++) {
                int row = wm * 64 + mt * 16 + (sub & 1) * 8 + l8;
                int col = ks * 16 + (sub >> 1) * 8;
                ldsm4(aF[mt][0], aF[mt][1], aF[mt][2], aF[mt][3],
                      ab + (row * GSTR + col) * 2);
            }
            #pragma unroll
            for (int p = 0; p < 2; p++) {
                int row = wn * 32 + p * 16 + (sub >> 1) * 8 + l8;
                int col = ks * 16 + (sub & 1) * 8;
                uint32_t r0, r1, r2, r3;
                ldsm4(r0, r1, r2, r3, bb + (row * GSTR + col) * 2);
                bF[2*p][0] = r0;   bF[2*p][1] = r1;
                bF[2*p+1][0] = r2; bF[2*p+1][1] = r3;
            }
            #pragma unroll
            for (int mt = 0; mt < 4; mt++)
                #pragma unroll
                for (int nt = 0; nt < 4; nt++)
                    mma_h(acc[mt][nt][0], acc[mt][nt][1],
                          acc[mt][nt][2], acc[mt][nt][3],
                          aF[mt][0], aF[mt][1], aF[mt][2], aF[mt][3],
                          bF[nt][0], bF[nt][1]);
        }
        __syncthreads();
    }

    #pragma unroll
    for (int mt = 0; mt < 4; mt++) {
        int r0 = bm + wm * 64 + mt * 16 + g, r1 = r0 + 8;
        #pragma unroll
        for (int nt = 0; nt < 4; nt++) {
            int c = bn + wn * 32 + nt * 8 + 2 * tg;
            float b0 = bias ? bias[c] : 0.f, b1 = bias ? bias[c + 1] : 0.f;
            float v00 = acc[mt][nt][0] + b0, v01 = acc[mt][nt][1] + b1;
            float v10 = acc[mt][nt][2] + b0, v11 = acc[mt][nt][3] + b1;
            if (OUTH) {
                fp16* C = (fp16*)Cv;
                if (r0 < M) *(uint32_t*)(C + (long)r0 * ldc + c) = packh(v00, v01);
                if (r1 < M) *(uint32_t*)(C + (long)r1 * ldc + c) = packh(v10, v11);
            } else {
                float* C = (float*)Cv;
                if (r0 < M) *(float2*)(C + (long)r0 * ldc + c) = make_float2(v00, v01);
                if (r1 < M) *(float2*)(C + (long)r1 * ldc + c) = make_float2(v10, v11);
            }
        }
    }
}

// ---------------- fp16 flash attention ---------------------------------------
// Block = 128 q-rows of one (b,h). 8 warps x 16 rows. 64-key tiles, cp.async
// double-buffered K/V. P stays in registers (S C-frag == PV A-frag layout).
#define KSTR 136
#define FL_SMEM (4 * 64 * KSTR * 2)
__global__ __launch_bounds__(256, 1)
void flash_h_kernel(fp16* __restrict__ qo,
                    const fp16* __restrict__ kbuf,
                    const fp16* __restrict__ vbuf) {
    const int qt = blockIdx.x, h = blockIdx.y, b = blockIdx.z;
    const int tid = threadIdx.x;
    const int w = tid >> 5, lane = tid & 31;
    const int g = lane >> 2, tg = lane & 3;
    const int l8 = lane & 7, sub = lane >> 3;
    const float scale = 0.08838834764831845f;

    extern __shared__ fp16 sm[];
    uint32_t smB = smem_u32(sm);
    const uint32_t tileB = 64 * KSTR * 2;

    fp16* qb = qo + (long)b * KSEL_ * D_ + (long)h * HD_;
    const fp16* kb = kbuf + (long)b * S2_ * D_ + (long)h * HD_;
    const fp16* vb = vbuf + (long)b * S2_ * D_ + (long)h * HD_;

    const int r0g = qt * 128 + w * 16 + g, r1g = r0g + 8;
    const bool v0 = r0g < KSEL_, v1 = r1g < KSEL_;

    uint32_t qf[8][4];
    {
        const fp16* q0 = qb + (long)r0g * D_;
        const fp16* q1 = qb + (long)r1g * D_;
        #pragma unroll
        for (int ks = 0; ks < 8; ks++) {
            int c0 = ks * 16 + 2 * tg;
            qf[ks][0] = v0 ? *(const uint32_t*)(q0 + c0)     : 0u;
            qf[ks][1] = v1 ? *(const uint32_t*)(q1 + c0)     : 0u;
            qf[ks][2] = v0 ? *(const uint32_t*)(q0 + c0 + 8) : 0u;
            qf[ks][3] = v1 ? *(const uint32_t*)(q1 + c0 + 8) : 0u;
        }
    }

    float oacc[16][4];
    #pragma unroll
    for (int nt = 0; nt < 16; nt++)
        #pragma unroll
        for (int q = 0; q < 4; q++) oacc[nt][q] = 0.f;
    float m0 = -1e30f, m1 = -1e30f, l0 = 0.f, l1 = 0.f;

    auto load_tile = [&](int t, int buf) {
        #pragma unroll
        for (int i = 0; i < 4; i++) {
            int idx = tid + i * 256;
            int r = idx >> 4, ch = (idx & 15) * 8;
            uint32_t dk = smB + buf * tileB + (r * KSTR + ch) * 2;
            uint32_t dv = smB + (2 + buf) * tileB + (r * KSTR + ch) * 2;
            long go = (long)(t * 64 + r) * D_ + ch;
            cp16(dk, kb + go, true);
            cp16(dv, vb + go, true);
        }
        CP_COMMIT();
    };

    load_tile(0, 0);
    const int NT = S2_ / 64;
    for (int t = 0; t < NT; ++t) {
        CP_WAIT0();
        __syncthreads();
        if (t + 1 < NT) load_tile(t + 1, (t + 1) & 1);
        uint32_t kbB = smB + (t & 1) * tileB;
        uint32_t vbB = smB + (2 + (t & 1)) * tileB;

        // S = Q K^T  (m16 x n64 x k128)
        float sa[8][4];
        #pragma unroll
        for (int j = 0; j < 8; j++)
            #pragma unroll
            for (int q = 0; q < 4; q++) sa[j][q] = 0.f;
        #pragma unroll
        for (int ks = 0; ks < 8; ks++) {
            #pragma unroll
            for (int nn = 0; nn < 2; nn++) {
                uint32_t b00,b01,b10,b11,b20,b21,b30,b31;
                {
                    int row = nn * 32 + (sub >> 1) * 8 + l8;
                    int col = ks * 16 + (sub & 1) * 8;
                    ldsm4(b00, b01, b10, b11, kbB + (row * KSTR + col) * 2);
                }
                {
                    int row = nn * 32 + 16 + (sub >> 1) * 8 + l8;
                    int col = ks * 16 + (sub & 1) * 8;
                    ldsm4(b20, b21, b30, b31, kbB + (row * KSTR + col) * 2);
                }
                int j0 = nn * 4;
                mma_h(sa[j0+0][0],sa[j0+0][1],sa[j0+0][2],sa[j0+0][3],
                      qf[ks][0],qf[ks][1],qf[ks][2],qf[ks][3], b00,b01);
                mma_h(sa[j0+1][0],sa[j0+1][1],sa[j0+1][2],sa[j0+1][3],
                      qf[ks][0],qf[ks][1],qf[ks][2],qf[ks][3], b10,b11);
                mma_h(sa[j0+2][0],sa[j0+2][1],sa[j0+2][2],sa[j0+2][3],
                      qf[ks][0],qf[ks][1],qf[ks][2],qf[ks][3], b20,b21);
                mma_h(sa[j0+3][0],sa[j0+3][1],sa[j0+3][2],sa[j0+3][3],
                      qf[ks][0],qf[ks][1],qf[ks][2],qf[ks][3], b30,b31);
            }
        }

        // scaled online softmax
        float rm0 = -1e30f, rm1 = -1e30f;
        #pragma unroll
        for (int j = 0; j < 8; j++) {
            sa[j][0] *= scale; sa[j][1] *= scale;
            sa[j][2] *= scale; sa[j][3] *= scale;
            rm0 = fmaxf(rm0, fmaxf(sa[j][0], sa[j][1]));
            rm1 = fmaxf(rm1, fmaxf(sa[j][2], sa[j][3]));
        }
        rm0 = fmaxf(rm0, __shfl_xor_sync(0xffffffffu, rm0, 1));
        rm0 = fmaxf(rm0, __shfl_xor_sync(0xffffffffu, rm0, 2));
        rm1 = fmaxf(rm1, __shfl_xor_sync(0xffffffffu, rm1, 1));
        rm1 = fmaxf(rm1, __shfl_xor_sync(0xffffffffu, rm1, 2));
        float mn0 = fmaxf(m0, rm0), mn1 = fmaxf(m1, rm1);
        float cr0 = __expf(m0 - mn0), cr1 = __expf(m1 - mn1);
        float ps0 = 0.f, ps1 = 0.f;
        #pragma unroll
        for (int j = 0; j < 8; j++) {
            sa[j][0] = __expf(sa[j][0] - mn0);
            sa[j][1] = __expf(sa[j][1] - mn0);
            sa[j][2] = __expf(sa[j][2] - mn1);
            sa[j][3] = __expf(sa[j][3] - mn1);
            ps0 += sa[j][0] + sa[j][1];
            ps1 += sa[j][2] + sa[j][3];
        }
        ps0 += __shfl_xor_sync(0xffffffffu, ps0, 1);
        ps0 += __shfl_xor_sync(0xffffffffu, ps0, 2);
        ps1 += __shfl_xor_sync(0xffffffffu, ps1, 1);
        ps1 += __shfl_xor_sync(0xffffffffu, ps1, 2);
        l0 = l0 * cr0 + ps0;  l1 = l1 * cr1 + ps1;
        m0 = mn0;             m1 = mn1;
        #pragma unroll
        for (int nt = 0; nt < 16; nt++) {
            oacc[nt][0] *= cr0; oacc[nt][1] *= cr0;
            oacc[nt][2] *= cr1; oacc[nt][3] *= cr1;
        }

        // O += P V  (P from registers; V via ldmatrix.trans)
        #pragma unroll
        for (int kk = 0; kk < 4; kk++) {
            uint32_t a0 = packh(sa[2*kk][0],   sa[2*kk][1]);
            uint32_t a1 = packh(sa[2*kk][2],   sa[2*kk][3]);
            uint32_t a2 = packh(sa[2*kk+1][0], sa[2*kk+1][1]);
            uint32_t a3 = packh(sa[2*kk+1][2], sa[2*kk+1][3]);
            #pragma unroll
            for (int nn = 0; nn < 8; nn++) {
                uint32_t r0, r1, r2, r3;
                int row = kk * 16 + (sub & 1) * 8 + l8;
                int col = nn * 16 + (sub >> 1) * 8;
                ldsm4t(r0, r1, r2, r3, vbB + (row * KSTR + col) * 2);
                mma_h(oacc[2*nn][0],   oacc[2*nn][1],   oacc[2*nn][2],   oacc[2*nn][3],
                      a0, a1, a2, a3, r0, r1);
                mma_h(oacc[2*nn+1][0], oacc[2*nn+1][1], oacc[2*nn+1][2], oacc[2*nn+1][3],
                      a0, a1, a2, a3, r2, r3);
            }
        }
        __syncthreads();
    }

    float i0 = 1.0f / l0, i1 = 1.0f / l1;
    #pragma unroll
    for (int nt = 0; nt < 16; nt++) {
        int c = nt * 8 + 2 * tg;
        if (v0) *(uint32_t*)(qb + (long)r0g * D_ + c) =
            packh(oacc[nt][0] * i0, oacc[nt][1] * i0);
        if (v1) *(uint32_t*)(qb + (long)r1g * D_ + c) =
            packh(oacc[nt][2] * i1, oacc[nt][3] * i1);
    }
}

// ---------------- final fuse -------------------------------------------------
__global__ void final_kernel(const float* __restrict__ base,
                             const float* __restrict__ attn,
                             const float* __restrict__ cth,
                             float* __restrict__ out) {
    int row = blockIdx.x;
    int tid = threadIdx.x;
    bool ok = (d_confsum * (1.0f / (float)(B_ * S2_)) > cth[0]);
    float g  = 1.0f / (1.0f + expf(-d_gatel[row]));
    float hg = 0.5f * g;
    int ro   = d_rowof[row];
    const float4* bp = (const float4*)(base + (long)row * D_);
    const float4* ap = (ro >= 0) ? (const float4*)(attn + (long)ro * D_) : bp;
    float4* op = (float4*)(out + (long)row * D_);
    float4 x = bp[tid], a = ap[tid], y;
    y.x = ok ? x.x + hg * a.x : x.x;
    y.y = ok ? x.y + hg * a.y : x.y;
    y.z = ok ? x.z + hg * a.z : x.z;
    y.w = ok ? x.w + hg * a.w : x.w;
    op[tid] = y;
}

// ---------------- host -------------------------------------------------------
static void run_gemm(bool gather, bool outh,
                     const fp16* A, const fp16* W, const float* bias, void* C,
                     const int* grows, int M, int N, int Kd,
                     int lda, int ldb, int ldc) {
    dim3 grid(N / 128, (M + 127) / 128, 1);
    if (gather) {
        if (outh) gemm_h_kernel<true, true><<<grid, 256>>>(A, W, bias, C, grows, M, N, Kd, lda, ldb, ldc);
        else      gemm_h_kernel<true, false><<<grid, 256>>>(A, W, bias, C, grows, M, N, Kd, lda, ldb, ldc);
    } else {
        if (outh) gemm_h_kernel<false, true><<<grid, 256>>>(A, W, bias, C, grows, M, N, Kd, lda, ldb, ldc);
        else      gemm_h_kernel<false, false><<<grid, 256>>>(A, W, bias, C, grows, M, N, Kd, lda, ldb, ldc);
    }
}
static void cvt(const float* s, fp16* d, long n) {
    int n4 = (int)(n / 4);
    cvt_kernel<<<(n4 + 255) / 256, 256>>>((const float4*)s, (uint2*)d, n4);
}

extern "C" void kernel_launch(void* const* d_in, const int* in_sizes, int n_in,
                              void* d_out, int out_size) {
    const float* base     = (const float*)d_in[0];
    const float* scaffold = (const float*)d_in[1];
    const float* spw      = (const float*)d_in[2];
    const float* spb      = (const float*)d_in[3];
    const float* tkw      = (const float*)d_in[4];
    const float* tkb      = (const float*)d_in[5];
    const float* ipw      = (const float*)d_in[6];
    const float* ipb      = (const float*)d_in[7];
    const float* opw      = (const float*)d_in[8];
    const float* opb      = (const float*)d_in[9];
    const float* gw       = (const float*)d_in[10];
    const float* gb       = (const float*)d_in[11];
    const float* cth      = (const float*)d_in[12];
    float* out            = (float*)d_out;

    float* p_ws; float* p_scores; float* p_gatel; int* p_grows;
    cudaGetSymbolAddress((void**)&p_ws,     d_ws);
    cudaGetSymbolAddress((void**)&p_scores, d_scores);
    cudaGetSymbolAddress((void**)&p_gatel,  d_gatel);
    cudaGetSymbolAddress((void**)&p_grows,  d_grows);

    float* p_attn = p_ws + WS_ATTN;
    fp16* p_kh    = (fp16*)(p_ws + WS_KH);
    fp16* p_vh    = (fp16*)(p_ws + WS_VH);
    fp16* p_scafh = (fp16*)(p_ws + WS_SCAFH);
    fp16* p_spwh  = (fp16*)(p_ws + WS_SPWH);
    fp16* p_ipwh  = (fp16*)(p_ws + WS_IPWH);
    fp16* p_opwh  = (fp16*)(p_ws + WS_OPWH);
    fp16* p_baseh = (fp16*)(out + DO_BASEH);
    fp16* p_scfh  = (fp16*)(out + DO_SCFH);
    fp16* p_qh    = (fp16*)(out + DO_QH);

    cudaFuncSetAttribute(flash_h_kernel,
                         cudaFuncAttributeMaxDynamicSharedMemorySize, FL_SMEM);

    init_kernel<<<64, 256>>>();
    // exact fp32 scores/gate (reads d_in only)
    rowdot2_kernel<<<(B_ * S_ * 32 + 255) / 256, 256>>>(
        base, tkw, tkb, gw, gb, p_scores, p_gatel, B_ * S_);
    {
        dim3 sg(S_ / 256, B_);
        select_kernel<<<sg, 256>>>();
    }

    // fp16 conversions (disjoint destinations)
    cvt(base,     p_baseh, (long)B_ * S_ * D_);
    cvt(scaffold, p_scfh,  (long)B_ * S2_ * SCAFD_);
    cvt(spw,      p_spwh,  (long)D_ * SCAFD_);
    cvt(ipw,      p_ipwh,  3L * D_ * D_);
    cvt(opw,      p_opwh,  (long)D_ * D_);

    // scaf_h = scaffold_h @ spw^T + spb
    run_gemm(false, true, p_scfh, p_spwh, spb, p_scafh, nullptr,
             B_ * S2_, D_, SCAFD_, SCAFD_, SCAFD_, D_);
    norm_kernel<<<(B_ * S2_ * 32 + 255) / 256, 256>>>(p_scafh);

    // k_h, v_h
    run_gemm(false, true, p_scafh, p_ipwh + (long)D_ * D_, ipb + D_, p_kh,
             nullptr, B_ * S2_, D_, D_, D_, D_, D_);
    run_gemm(false, true, p_scafh, p_ipwh + 2L * D_ * D_, ipb + 2 * D_, p_vh,
             nullptr, B_ * S2_, D_, D_, D_, D_, D_);

    // q_h = gather(base_h) @ wq^T + bq
    run_gemm(true, true, p_baseh, p_ipwh, ipb, p_qh, p_grows,
             BKROWS_, D_, D_, D_, D_, D_);

    // flash attention (o_h overwrites q_h)
    {
        dim3 grid((KSEL_ + 127) / 128, H_, B_);
        flash_h_kernel<<<grid, 256, FL_SMEM>>>(p_qh, p_kh, p_vh);
    }

    // attn = o_h @ opw^T + opb (fp32 out; k/v dead)
    run_gemm(false, false, p_qh, p_opwh, opb, p_attn, nullptr,
             BKROWS_, D_, D_, D_, D_, D_);

    final_kernel<<<B_ * S_, 256>>>(base, p_attn, cth, out);
}

// round 17
// speedup vs baseline: 7.8135x; 1.0173x over previous
#include <cuda_runtime.h>
#include <cuda_fp16.h>
#include <math.h>
#include <stdint.h>

#define B_      4
#define S_      4096
#define S2_     2048
#define D_      1024
#define SCAFD_  768
#define H_      8
#define HD_     128
#define KSEL_   2549
#define BKROWS_ (B_*KSEL_)           // 10196

typedef __half fp16;

// ---------------- scratch (offsets in floats; lifetimes disjoint) ------------
// d_ws: ATTN fp32 [0,10440704)         live: attn GEMM .. final
//       KH fp16   [0,4194304)          live: k GEMM .. flash (dead before ATTN)
//       VH fp16   [4194304,8388608)    live: v GEMM .. flash
//       SCAFH     [8388608,12582912)   live: scaf GEMM .. v GEMM
//       SPWH      [12582912,12976128)  393216 floats  (D*SCAFD halves)
//       IPWH      [12976128,14548992)  1572864 floats (3*D*D halves)
//       OPWH      [14548992,15073280)  524288 floats  (D*D halves)
#define WS_ATTN   0L
#define WS_KH     0L
#define WS_VH     4194304L
#define WS_SCAFH  8388608L
#define WS_SPWH   12582912L
#define WS_IPWH   12976128L
#define WS_OPWH   14548992L
__device__ float d_ws[16777216];     // 67.1 MB
__device__ float d_scores[B_*S_];
__device__ float d_gatel [B_*S_];
__device__ int   d_grows [BKROWS_];
__device__ int   d_rowof [B_*S_];
__device__ int   d_cnt   [B_];
__device__ float d_confsum;
// d_out scratch: BASEH fp16 [0,8388608) live cvt..q-GEMM; SCFH [8388608,11534336)
// live cvt..scaf-GEMM; QH (q then o) [11534336,16754688) live q-GEMM..attn-GEMM.
// final_kernel rewrites all of d_out last.
#define DO_BASEH 0L
#define DO_SCFH  8388608L
#define DO_QH    11534336L

// ---------------- helpers ----------------------------------------------------
__device__ __forceinline__ uint32_t smem_u32(const void* p) {
    return (uint32_t)__cvta_generic_to_shared(p);
}
__device__ __forceinline__ void cp16(uint32_t s, const void* g, bool v) {
    asm volatile("cp.async.cg.shared.global [%0], [%1], 16, %2;"
                 :: "r"(s), "l"(g), "r"(v ? 16 : 0));
}
#define CP_COMMIT() asm volatile("cp.async.commit_group;")
#define CP_WAIT0()  asm volatile("cp.async.wait_group 0;")
__device__ __forceinline__ void ldsm4(uint32_t& r0, uint32_t& r1,
                                      uint32_t& r2, uint32_t& r3, uint32_t a) {
    asm volatile("ldmatrix.sync.aligned.m8n8.x4.shared.b16 {%0,%1,%2,%3},[%4];"
                 : "=r"(r0), "=r"(r1), "=r"(r2), "=r"(r3) : "r"(a));
}
__device__ __forceinline__ void ldsm4t(uint32_t& r0, uint32_t& r1,
                                       uint32_t& r2, uint32_t& r3, uint32_t a) {
    asm volatile("ldmatrix.sync.aligned.m8n8.x4.trans.shared.b16 {%0,%1,%2,%3},[%4];"
                 : "=r"(r0), "=r"(r1), "=r"(r2), "=r"(r3) : "r"(a));
}
__device__ __forceinline__ void mma_h(float& d0, float& d1, float& d2, float& d3,
                                      uint32_t a0, uint32_t a1, uint32_t a2, uint32_t a3,
                                      uint32_t b0, uint32_t b1) {
    asm volatile(
        "mma.sync.aligned.m16n8k16.row.col.f32.f16.f16.f32 "
        "{%0,%1,%2,%3}, {%4,%5,%6,%7}, {%8,%9}, {%0,%1,%2,%3};"
        : "+f"(d0), "+f"(d1), "+f"(d2), "+f"(d3)
        : "r"(a0), "r"(a1), "r"(a2), "r"(a3), "r"(b0), "r"(b1));
}
__device__ __forceinline__ uint32_t packh(float lo, float hi) {
    __half2 h = __floats2half2_rn(lo, hi);
    return *(uint32_t*)&h;
}

// ---------------- fp32 -> fp16 -----------------------------------------------
__global__ void cvt_kernel(const float4* __restrict__ s, uint2* __restrict__ d, int n4) {
    int i = blockIdx.x * blockDim.x + threadIdx.x;
    if (i >= n4) return;
    float4 v = s[i];
    d[i] = make_uint2(packh(v.x, v.y), packh(v.z, v.w));
}

// ---------------- init -------------------------------------------------------
__global__ void init_kernel() {
    int i = blockIdx.x * blockDim.x + threadIdx.x;
    if (i < B_*S_) d_rowof[i] = -1;
    if (i < B_)    d_cnt[i]   = 0;
    if (i == 0)    d_confsum  = 0.0f;
}

// ---------------- fused: exact fp32 dual row-dot + fp16 conversion ----------
// One warp per row of base: computes topk score + gate logit (fp32 exact)
// AND emits the fp16 copy of the row. Single pass over 134 MB.
__global__ void rowdot2cvt_kernel(const float* __restrict__ X,
                                  const float* __restrict__ w1, const float* __restrict__ b1,
                                  const float* __restrict__ w2, const float* __restrict__ b2,
                                  float* __restrict__ o1, float* __restrict__ o2,
                                  uint2* __restrict__ xh, int nrows) {
    int warp = (blockIdx.x * blockDim.x + threadIdx.x) >> 5;
    int lane = threadIdx.x & 31;
    if (warp >= nrows) return;
    const float4* x4 = (const float4*)(X + (long)warp * D_);
    const float4* u4 = (const float4*)w1;
    const float4* v4 = (const float4*)w2;
    uint2* out16 = xh + (long)warp * (D_ / 4);
    float s1 = 0.f, s2 = 0.f;
    #pragma unroll
    for (int i = lane; i < D_/4; i += 32) {
        float4 a = x4[i], u = u4[i], v = v4[i];
        s1 += a.x*u.x + a.y*u.y + a.z*u.z + a.w*u.w;
        s2 += a.x*v.x + a.y*v.y + a.z*v.z + a.w*v.w;
        out16[i] = make_uint2(packh(a.x, a.y), packh(a.z, a.w));
    }
    #pragma unroll
    for (int off = 16; off; off >>= 1) {
        s1 += __shfl_xor_sync(0xffffffffu, s1, off);
        s2 += __shfl_xor_sync(0xffffffffu, s2, off);
    }
    if (lane == 0) { o1[warp] = s1 + b1[0]; o2[warp] = s2 + b2[0]; }
}

// ---------------- mean row-norm of scaf_h ------------------------------------
__global__ void norm_kernel(const fp16* __restrict__ scaf) {
    int warp = (blockIdx.x * blockDim.x + threadIdx.x) >> 5;
    int lane = threadIdx.x & 31;
    if (warp >= B_*S2_) return;
    const __half2* x = (const __half2*)(scaf + (long)warp * D_);
    float s = 0.f;
    for (int i = lane; i < D_/2; i += 32) {
        float2 f = __half22float2(x[i]);
        s += f.x*f.x + f.y*f.y;
    }
    #pragma unroll
    for (int off = 16; off; off >>= 1) s += __shfl_xor_sync(0xffffffffu, s, off);
    if (lane == 0) atomicAdd(&d_confsum, sqrtf(s));
}

// ---------------- exact top-K via rank counting ------------------------------
__global__ void select_kernel() {
    __shared__ float sh[S_];
    int b = blockIdx.y;
    const float* sc = d_scores + b * S_;
    for (int i = threadIdx.x; i < S_; i += 256) sh[i] = sc[i];
    __syncthreads();
    int cand = blockIdx.x * 256 + threadIdx.x;
    float myv = sh[cand];
    int cnt = 0;
    for (int j = 0; j < S_; j += 4) {
        float4 v = *(const float4*)&sh[j];
        cnt += (v.x > myv) || (v.x == myv && (j + 0) < cand);
        cnt += (v.y > myv) || (v.y == myv && (j + 1) < cand);
        cnt += (v.z > myv) || (v.z == myv && (j + 2) < cand);
        cnt += (v.w > myv) || (v.w == myv && (j + 3) < cand);
    }
    if (cnt < KSEL_) {
        int pos = atomicAdd(&d_cnt[b], 1);
        d_grows[b * KSEL_ + pos] = b * S_ + cand;
        d_rowof[b * S_ + cand]   = b * KSEL_ + pos;
    }
}

// ---------------- fp16 GEMM: C = A @ W^T + bias ------------------------------
// 128x128 tile, BK=32, 8 warps (2m x 4n), each 64x32. cp.async 2-stage.
// __launch_bounds__(256,2): 2 blocks/SM (40KB smem, <=128 regs) for latency hiding.
#define GSTR 40
template <bool GATHER, bool OUTH>
__global__ __launch_bounds__(256, 2)
void gemm_h_kernel(const fp16* __restrict__ A, const fp16* __restrict__ W,
                   const float* __restrict__ bias, void* __restrict__ Cv,
                   const int* __restrict__ grows,
                   int M, int N, int Kd, int lda, int ldb, int ldc) {
    __shared__ fp16 sA[2][128 * GSTR];
    __shared__ fp16 sB[2][128 * GSTR];
    const int tid = threadIdx.x;
    const int w = tid >> 5, lane = tid & 31;
    const int g = lane >> 2, tg = lane & 3;
    const int l8 = lane & 7, sub = lane >> 3;
    const int wm = w & 1, wn = w >> 1;
    const int bm = blockIdx.y * 128, bn = blockIdx.x * 128;

    const int crow = tid >> 1, cc = (tid & 1) * 16;
    bool av = (bm + crow) < M;
    long arow = av ? (GATHER ? (long)grows[bm + crow] : (long)(bm + crow)) : 0;
    const fp16* agp = A + arow * lda;
    const fp16* bgp = W + (long)(bn + crow) * ldb;
    uint32_t saB = smem_u32(&sA[0][0]), sbB = smem_u32(&sB[0][0]);
    const uint32_t stg = 128 * GSTR * 2;
    uint32_t da = saB + (crow * GSTR + cc) * 2;
    uint32_t db = sbB + (crow * GSTR + cc) * 2;

    float acc[4][4][4];
    #pragma unroll
    for (int i = 0; i < 4; i++)
        #pragma unroll
        for (int j = 0; j < 4; j++)
            #pragma unroll
            for (int q = 0; q < 4; q++) acc[i][j][q] = 0.f;

    const int niter = Kd / 32;
    cp16(da, agp + cc, av);      cp16(da + 16, agp + cc + 8, av);
    cp16(db, bgp + cc, true);    cp16(db + 16, bgp + cc + 8, true);
    CP_COMMIT();

    for (int it = 0; it < niter; ++it) {
        CP_WAIT0();
        __syncthreads();
        if (it + 1 < niter) {
            int k0 = (it + 1) * 32;
            uint32_t off = ((it + 1) & 1) * stg;
            cp16(da + off,      agp + k0 + cc,     av);
            cp16(da + off + 16, agp + k0 + cc + 8, av);
            cp16(db + off,      bgp + k0 + cc,     true);
            cp16(db + off + 16, bgp + k0 + cc + 8, true);
            CP_COMMIT();
        }
        uint32_t ab = saB + (it & 1) * stg, bb = sbB + (it & 1) * stg;
        #pragma unroll
        for (int ks = 0; ks < 2; ks++) {
            uint32_t aF[4][4], bF[4][2];
            #pragma unroll
            for (int mt = 0; mt < 4; mt++) {
                int row = wm * 64 + mt * 16 + (sub & 1) * 8 + l8;
                int col = ks * 16 + (sub >> 1) * 8;
                ldsm4(aF[mt][0], aF[mt][1], aF[mt][2], aF[mt][3],
                      ab + (row * GSTR + col) * 2);
            }
            #pragma unroll
            for (int p = 0; p < 2; p++) {
                int row = wn * 32 + p * 16 + (sub >> 1) * 8 + l8;
                int col = ks * 16 + (sub & 1) * 8;
                uint32_t r0, r1, r2, r3;
                ldsm4(r0, r1, r2, r3, bb + (row * GSTR + col) * 2);
                bF[2*p][0] = r0;   bF[2*p][1] = r1;
                bF[2*p+1][0] = r2; bF[2*p+1][1] = r3;
            }
            #pragma unroll
            for (int mt = 0; mt < 4; mt++)
                #pragma unroll
                for (int nt = 0; nt < 4; nt++)
                    mma_h(acc[mt][nt][0], acc[mt][nt][1],
                          acc[mt][nt][2], acc[mt][nt][3],
                          aF[mt][0], aF[mt][1], aF[mt][2], aF[mt][3],
                          bF[nt][0], bF[nt][1]);
        }
        __syncthreads();
    }

    #pragma unroll
    for (int mt = 0; mt < 4; mt++) {
        int r0 = bm + wm * 64 + mt * 16 + g, r1 = r0 + 8;
        #pragma unroll
        for (int nt = 0; nt < 4; nt++) {
            int c = bn + wn * 32 + nt * 8 + 2 * tg;
            float b0 = bias ? bias[c] : 0.f, b1 = bias ? bias[c + 1] : 0.f;
            float v00 = acc[mt][nt][0] + b0, v01 = acc[mt][nt][1] + b1;
            float v10 = acc[mt][nt][2] + b0, v11 = acc[mt][nt][3] + b1;
            if (OUTH) {
                fp16* C = (fp16*)Cv;
                if (r0 < M) *(uint32_t*)(C + (long)r0 * ldc + c) = packh(v00, v01);
                if (r1 < M) *(uint32_t*)(C + (long)r1 * ldc + c) = packh(v10, v11);
            } else {
                float* C = (float*)Cv;
                if (r0 < M) *(float2*)(C + (long)r0 * ldc + c) = make_float2(v00, v01);
                if (r1 < M) *(float2*)(C + (long)r1 * ldc + c) = make_float2(v10, v11);
            }
        }
    }
}

// ---------------- fp16 flash attention ---------------------------------------
// Block = 128 q-rows of one (b,h). 8 warps x 16 rows. 64-key tiles, cp.async
// double-buffered K/V. P stays in registers (S C-frag == PV A-frag layout).
#define KSTR 136
#define FL_SMEM (4 * 64 * KSTR * 2)
__global__ __launch_bounds__(256, 1)
void flash_h_kernel(fp16* __restrict__ qo,
                    const fp16* __restrict__ kbuf,
                    const fp16* __restrict__ vbuf) {
    const int qt = blockIdx.x, h = blockIdx.y, b = blockIdx.z;
    const int tid = threadIdx.x;
    const int w = tid >> 5, lane = tid & 31;
    const int g = lane >> 2, tg = lane & 3;
    const int l8 = lane & 7, sub = lane >> 3;
    const float scale = 0.08838834764831845f;

    extern __shared__ fp16 sm[];
    uint32_t smB = smem_u32(sm);
    const uint32_t tileB = 64 * KSTR * 2;

    fp16* qb = qo + (long)b * KSEL_ * D_ + (long)h * HD_;
    const fp16* kb = kbuf + (long)b * S2_ * D_ + (long)h * HD_;
    const fp16* vb = vbuf + (long)b * S2_ * D_ + (long)h * HD_;

    const int r0g = qt * 128 + w * 16 + g, r1g = r0g + 8;
    const bool v0 = r0g < KSEL_, v1 = r1g < KSEL_;

    uint32_t qf[8][4];
    {
        const fp16* q0 = qb + (long)r0g * D_;
        const fp16* q1 = qb + (long)r1g * D_;
        #pragma unroll
        for (int ks = 0; ks < 8; ks++) {
            int c0 = ks * 16 + 2 * tg;
            qf[ks][0] = v0 ? *(const uint32_t*)(q0 + c0)     : 0u;
            qf[ks][1] = v1 ? *(const uint32_t*)(q1 + c0)     : 0u;
            qf[ks][2] = v0 ? *(const uint32_t*)(q0 + c0 + 8) : 0u;
            qf[ks][3] = v1 ? *(const uint32_t*)(q1 + c0 + 8) : 0u;
        }
    }

    float oacc[16][4];
    #pragma unroll
    for (int nt = 0; nt < 16; nt++)
        #pragma unroll
        for (int q = 0; q < 4; q++) oacc[nt][q] = 0.f;
    float m0 = -1e30f, m1 = -1e30f, l0 = 0.f, l1 = 0.f;

    auto load_tile = [&](int t, int buf) {
        #pragma unroll
        for (int i = 0; i < 4; i++) {
            int idx = tid + i * 256;
            int r = idx >> 4, ch = (idx & 15) * 8;
            uint32_t dk = smB + buf * tileB + (r * KSTR + ch) * 2;
            uint32_t dv = smB + (2 + buf) * tileB + (r * KSTR + ch) * 2;
            long go = (long)(t * 64 + r) * D_ + ch;
            cp16(dk, kb + go, true);
            cp16(dv, vb + go, true);
        }
        CP_COMMIT();
    };

    load_tile(0, 0);
    const int NT = S2_ / 64;
    for (int t = 0; t < NT; ++t) {
        CP_WAIT0();
        __syncthreads();
        if (t + 1 < NT) load_tile(t + 1, (t + 1) & 1);
        uint32_t kbB = smB + (t & 1) * tileB;
        uint32_t vbB = smB + (2 + (t & 1)) * tileB;

        // S = Q K^T  (m16 x n64 x k128)
        float sa[8][4];
        #pragma unroll
        for (int j = 0; j < 8; j++)
            #pragma unroll
            for (int q = 0; q < 4; q++) sa[j][q] = 0.f;
        #pragma unroll
        for (int ks = 0; ks < 8; ks++) {
            #pragma unroll
            for (int nn = 0; nn < 2; nn++) {
                uint32_t b00,b01,b10,b11,b20,b21,b30,b31;
                {
                    int row = nn * 32 + (sub >> 1) * 8 + l8;
                    int col = ks * 16 + (sub & 1) * 8;
                    ldsm4(b00, b01, b10, b11, kbB + (row * KSTR + col) * 2);
                }
                {
                    int row = nn * 32 + 16 + (sub >> 1) * 8 + l8;
                    int col = ks * 16 + (sub & 1) * 8;
                    ldsm4(b20, b21, b30, b31, kbB + (row * KSTR + col) * 2);
                }
                int j0 = nn * 4;
                mma_h(sa[j0+0][0],sa[j0+0][1],sa[j0+0][2],sa[j0+0][3],
                      qf[ks][0],qf[ks][1],qf[ks][2],qf[ks][3], b00,b01);
                mma_h(sa[j0+1][0],sa[j0+1][1],sa[j0+1][2],sa[j0+1][3],
                      qf[ks][0],qf[ks][1],qf[ks][2],qf[ks][3], b10,b11);
                mma_h(sa[j0+2][0],sa[j0+2][1],sa[j0+2][2],sa[j0+2][3],
                      qf[ks][0],qf[ks][1],qf[ks][2],qf[ks][3], b20,b21);
                mma_h(sa[j0+3][0],sa[j0+3][1],sa[j0+3][2],sa[j0+3][3],
                      qf[ks][0],qf[ks][1],qf[ks][2],qf[ks][3], b30,b31);
            }
        }

        // scaled online softmax
        float rm0 = -1e30f, rm1 = -1e30f;
        #pragma unroll
        for (int j = 0; j < 8; j++) {
            sa[j][0] *= scale; sa[j][1] *= scale;
            sa[j][2] *= scale; sa[j][3] *= scale;
            rm0 = fmaxf(rm0, fmaxf(sa[j][0], sa[j][1]));
            rm1 = fmaxf(rm1, fmaxf(sa[j][2], sa[j][3]));
        }
        rm0 = fmaxf(rm0, __shfl_xor_sync(0xffffffffu, rm0, 1));
        rm0 = fmaxf(rm0, __shfl_xor_sync(0xffffffffu, rm0, 2));
        rm1 = fmaxf(rm1, __shfl_xor_sync(0xffffffffu, rm1, 1));
        rm1 = fmaxf(rm1, __shfl_xor_sync(0xffffffffu, rm1, 2));
        float mn0 = fmaxf(m0, rm0), mn1 = fmaxf(m1, rm1);
        float cr0 = __expf(m0 - mn0), cr1 = __expf(m1 - mn1);
        float ps0 = 0.f, ps1 = 0.f;
        #pragma unroll
        for (int j = 0; j < 8; j++) {
            sa[j][0] = __expf(sa[j][0] - mn0);
            sa[j][1] = __expf(sa[j][1] - mn0);
            sa[j][2] = __expf(sa[j][2] - mn1);
            sa[j][3] = __expf(sa[j][3] - mn1);
            ps0 += sa[j][0] + sa[j][1];
            ps1 += sa[j][2] + sa[j][3];
        }
        ps0 += __shfl_xor_sync(0xffffffffu, ps0, 1);
        ps0 += __shfl_xor_sync(0xffffffffu, ps0, 2);
        ps1 += __shfl_xor_sync(0xffffffffu, ps1, 1);
        ps1 += __shfl_xor_sync(0xffffffffu, ps1, 2);
        l0 = l0 * cr0 + ps0;  l1 = l1 * cr1 + ps1;
        m0 = mn0;             m1 = mn1;
        #pragma unroll
        for (int nt = 0; nt < 16; nt++) {
            oacc[nt][0] *= cr0; oacc[nt][1] *= cr0;
            oacc[nt][2] *= cr1; oacc[nt][3] *= cr1;
        }

        // O += P V  (P from registers; V via ldmatrix.trans)
        #pragma unroll
        for (int kk = 0; kk < 4; kk++) {
            uint32_t a0 = packh(sa[2*kk][0],   sa[2*kk][1]);
            uint32_t a1 = packh(sa[2*kk][2],   sa[2*kk][3]);
            uint32_t a2 = packh(sa[2*kk+1][0], sa[2*kk+1][1]);
            uint32_t a3 = packh(sa[2*kk+1][2], sa[2*kk+1][3]);
            #pragma unroll
            for (int nn = 0; nn < 8; nn++) {
                uint32_t r0, r1, r2, r3;
                int row = kk * 16 + (sub & 1) * 8 + l8;
                int col = nn * 16 + (sub >> 1) * 8;
                ldsm4t(r0, r1, r2, r3, vbB + (row * KSTR + col) * 2);
                mma_h(oacc[2*nn][0],   oacc[2*nn][1],   oacc[2*nn][2],   oacc[2*nn][3],
                      a0, a1, a2, a3, r0, r1);
                mma_h(oacc[2*nn+1][0], oacc[2*nn+1][1], oacc[2*nn+1][2], oacc[2*nn+1][3],
                      a0, a1, a2, a3, r2, r3);
            }
        }
        __syncthreads();
    }

    float i0 = 1.0f / l0, i1 = 1.0f / l1;
    #pragma unroll
    for (int nt = 0; nt < 16; nt++) {
        int c = nt * 8 + 2 * tg;
        if (v0) *(uint32_t*)(qb + (long)r0g * D_ + c) =
            packh(oacc[nt][0] * i0, oacc[nt][1] * i0);
        if (v1) *(uint32_t*)(qb + (long)r1g * D_ + c) =
            packh(oacc[nt][2] * i1, oacc[nt][3] * i1);
    }
}

// ---------------- final fuse -------------------------------------------------
__global__ void final_kernel(const float* __restrict__ base,
                             const float* __restrict__ attn,
                             const float* __restrict__ cth,
                             float* __restrict__ out) {
    int row = blockIdx.x;
    int tid = threadIdx.x;
    bool ok = (d_confsum * (1.0f / (float)(B_ * S2_)) > cth[0]);
    float g  = 1.0f / (1.0f + expf(-d_gatel[row]));
    float hg = 0.5f * g;
    int ro   = d_rowof[row];
    const float4* bp = (const float4*)(base + (long)row * D_);
    const float4* ap = (ro >= 0) ? (const float4*)(attn + (long)ro * D_) : bp;
    float4* op = (float4*)(out + (long)row * D_);
    float4 x = bp[tid], a = ap[tid], y;
    y.x = ok ? x.x + hg * a.x : x.x;
    y.y = ok ? x.y + hg * a.y : x.y;
    y.z = ok ? x.z + hg * a.z : x.z;
    y.w = ok ? x.w + hg * a.w : x.w;
    op[tid] = y;
}

// ---------------- host -------------------------------------------------------
static void run_gemm(bool gather, bool outh,
                     const fp16* A, const fp16* W, const float* bias, void* C,
                     const int* grows, int M, int N, int Kd,
                     int lda, int ldb, int ldc) {
    dim3 grid(N / 128, (M + 127) / 128, 1);
    if (gather) {
        if (outh) gemm_h_kernel<true, true><<<grid, 256>>>(A, W, bias, C, grows, M, N, Kd, lda, ldb, ldc);
        else      gemm_h_kernel<true, false><<<grid, 256>>>(A, W, bias, C, grows, M, N, Kd, lda, ldb, ldc);
    } else {
        if (outh) gemm_h_kernel<false, true><<<grid, 256>>>(A, W, bias, C, grows, M, N, Kd, lda, ldb, ldc);
        else      gemm_h_kernel<false, false><<<grid, 256>>>(A, W, bias, C, grows, M, N, Kd, lda, ldb, ldc);
    }
}
static void cvt(const float* s, fp16* d, long n) {
    int n4 = (int)(n / 4);
    cvt_kernel<<<(n4 + 255) / 256, 256>>>((const float4*)s, (uint2*)d, n4);
}

extern "C" void kernel_launch(void* const* d_in, const int* in_sizes, int n_in,
                              void* d_out, int out_size) {
    const float* base     = (const float*)d_in[0];
    const float* scaffold = (const float*)d_in[1];
    const float* spw      = (const float*)d_in[2];
    const float* spb      = (const float*)d_in[3];
    const float* tkw      = (const float*)d_in[4];
    const float* tkb      = (const float*)d_in[5];
    const float* ipw      = (const float*)d_in[6];
    const float* ipb      = (const float*)d_in[7];
    const float* opw      = (const float*)d_in[8];
    const float* opb      = (const float*)d_in[9];
    const float* gw       = (const float*)d_in[10];
    const float* gb       = (const float*)d_in[11];
    const float* cth      = (const float*)d_in[12];
    float* out            = (float*)d_out;

    float* p_ws; float* p_scores; float* p_gatel; int* p_grows;
    cudaGetSymbolAddress((void**)&p_ws,     d_ws);
    cudaGetSymbolAddress((void**)&p_scores, d_scores);
    cudaGetSymbolAddress((void**)&p_gatel,  d_gatel);
    cudaGetSymbolAddress((void**)&p_grows,  d_grows);

    float* p_attn = p_ws + WS_ATTN;
    fp16* p_kh    = (fp16*)(p_ws + WS_KH);
    fp16* p_vh    = (fp16*)(p_ws + WS_VH);
    fp16* p_scafh = (fp16*)(p_ws + WS_SCAFH);
    fp16* p_spwh  = (fp16*)(p_ws + WS_SPWH);
    fp16* p_ipwh  = (fp16*)(p_ws + WS_IPWH);
    fp16* p_opwh  = (fp16*)(p_ws + WS_OPWH);
    fp16* p_baseh = (fp16*)(out + DO_BASEH);
    fp16* p_scfh  = (fp16*)(out + DO_SCFH);
    fp16* p_qh    = (fp16*)(out + DO_QH);

    cudaFuncSetAttribute(flash_h_kernel,
                         cudaFuncAttributeMaxDynamicSharedMemorySize, FL_SMEM);

    init_kernel<<<64, 256>>>();

    // fused: fp32-exact scores+gate AND base fp16 conversion (one pass)
    rowdot2cvt_kernel<<<(B_ * S_ * 32 + 255) / 256, 256>>>(
        base, tkw, tkb, gw, gb, p_scores, p_gatel,
        (uint2*)p_baseh, B_ * S_);
    {
        dim3 sg(S_ / 256, B_);
        select_kernel<<<sg, 256>>>();
    }

    // remaining fp16 conversions (disjoint destinations)
    cvt(scaffold, p_scfh,  (long)B_ * S2_ * SCAFD_);
    cvt(spw,      p_spwh,  (long)D_ * SCAFD_);
    cvt(ipw,      p_ipwh,  3L * D_ * D_);
    cvt(opw,      p_opwh,  (long)D_ * D_);

    // scaf_h = scaffold_h @ spw^T + spb
    run_gemm(false, true, p_scfh, p_spwh, spb, p_scafh, nullptr,
             B_ * S2_, D_, SCAFD_, SCAFD_, SCAFD_, D_);
    norm_kernel<<<(B_ * S2_ * 32 + 255) / 256, 256>>>(p_scafh);

    // k_h, v_h
    run_gemm(false, true, p_scafh, p_ipwh + (long)D_ * D_, ipb + D_, p_kh,
             nullptr, B_ * S2_, D_, D_, D_, D_, D_);
    run_gemm(false, true, p_scafh, p_ipwh + 2L * D_ * D_, ipb + 2 * D_, p_vh,
             nullptr, B_ * S2_, D_, D_, D_, D_, D_);

    // q_h = gather(base_h) @ wq^T + bq
    run_gemm(true, true, p_baseh, p_ipwh, ipb, p_qh, p_grows,
             BKROWS_, D_, D_, D_, D_, D_);

    // flash attention (o_h overwrites q_h)
    {
        dim3 grid((KSEL_ + 127) / 128, H_, B_);
        flash_h_kernel<<<grid, 256, FL_SMEM>>>(p_qh, p_kh, p_vh);
    }

    // attn = o_h @ opw^T + opb (fp32 out; k/v dead)
    run_gemm(false, false, p_qh, p_opwh, opb, p_attn, nullptr,
             BKROWS_, D_, D_, D_, D_, D_);

    final_kernel<<<B_ * S_, 256>>>(base, p_attn, cth, out);
}